// round 14
// baseline (speedup 1.0000x reference)
#include <cuda_runtime.h>
#include <cuda_bf16.h>
#include <math.h>
#include <stdint.h>

#define BATCH 4
#define CCH   256
#define CI    128
#define NPIX  4096
#define GROUPS 8
#define CPG   32
#define GSIZE (CPG*NPIX)
#define EPSV  1e-5f
#define KCONV 2304

// ---------------- scratch ----------------------------------------------------
__device__ float d_xs   [BATCH*CCH*NPIX];
__device__ float d_z    [BATCH*CCH*NPIX];
__device__ unsigned d_xsb[BATCH*128*NPIX];
__device__ unsigned d_yb [BATCH*64*NPIX];
__device__ unsigned d_wpk[65536];
__device__ __nv_bfloat16 d_wb [CCH*KCONV];
__device__ __nv_bfloat16 d_ws [CCH*KCONV];
__device__ __nv_bfloat16 d_xtb[BATCH*NPIX*CCH];
__device__ __nv_bfloat16 d_xts[BATCH*NPIX*CCH];
__device__ __nv_bfloat16 d_thb[BATCH*CI*NPIX];
__device__ __nv_bfloat16 d_phb[BATCH*CI*NPIX];
__device__ __nv_bfloat16 d_ttb[BATCH*NPIX*CI];
__device__ __nv_bfloat16 d_ptb[BATCH*NPIX*CI];
__device__ __nv_bfloat16 d_gb [BATCH*CI*NPIX];
__device__ float d_part1[32*16*2];
__device__ float d_part2[32*16*2];

// ---------------- helpers -----------------------------------------------------
__device__ __forceinline__ void mma_bf16(float* c,
    unsigned a0, unsigned a1, unsigned a2, unsigned a3,
    unsigned b0, unsigned b1) {
    asm volatile(
        "mma.sync.aligned.m16n8k16.row.col.f32.bf16.bf16.f32 "
        "{%0,%1,%2,%3}, {%4,%5,%6,%7}, {%8,%9}, {%0,%1,%2,%3};"
        : "+f"(c[0]), "+f"(c[1]), "+f"(c[2]), "+f"(c[3])
        : "r"(a0), "r"(a1), "r"(a2), "r"(a3), "r"(b0), "r"(b1));
}
__device__ __forceinline__ unsigned pack_bf(float hi, float lo) {
    unsigned u;
    asm("cvt.rn.bf16x2.f32 %0, %1, %2;" : "=r"(u) : "f"(hi), "f"(lo));
    return u;
}
__device__ __forceinline__ void cp16(uint32_t dst, const void* src) {
    asm volatile("cp.async.cg.shared.global [%0], [%1], 16;" :: "r"(dst), "l"(src));
}
__device__ __forceinline__ void cp16z(uint32_t dst, const void* src, int srcsz) {
    asm volatile("cp.async.cg.shared.global [%0], [%1], 16, %2;"
                 :: "r"(dst), "l"(src), "r"(srcsz));
}
__device__ __forceinline__ void cp_commit() {
    asm volatile("cp.async.commit_group;");
}
template<int N>
__device__ __forceinline__ void cp_wait() {
    asm volatile("cp.async.wait_group %0;" :: "n"(N));
}
__device__ __forceinline__ uint32_t smem_u32(const void* p) {
    return (uint32_t)__cvta_generic_to_shared(p);
}
__device__ __forceinline__ unsigned ldu(const float* p) {
    return __float_as_uint(*p);
}

// ---------------- precompute: conv weight 2-term bf16 split --------------------
__global__ void pack_w_bf_kernel(const float* __restrict__ w) {
    int k = blockIdx.x * 256 + threadIdx.x;
    int m = blockIdx.y;
    int c = k & 255, tap = k >> 8;
    float f = w[m*(CCH*9) + c*9 + tap];
    __nv_bfloat16 big = __float2bfloat16(f);
    d_wb[(size_t)m*KCONV + k] = big;
    d_ws[(size_t)m*KCONV + k] = __float2bfloat16(f - __bfloat162float(big));
}

// ---------------- precompute: x transpose + split -> [b][pix][c] bf16 ---------
__global__ void prep_x_kernel(const float* __restrict__ x) {
    __shared__ float t[32][33];
    int b  = blockIdx.z;
    int p0 = blockIdx.x * 32;
    int c0 = blockIdx.y * 32;
    int tx = threadIdx.x, ty = threadIdx.y;
    #pragma unroll
    for (int i = 0; i < 4; i++)
        t[ty + i*8][tx] = x[(size_t)(b*CCH + c0 + ty + i*8)*NPIX + p0 + tx];
    __syncthreads();
    #pragma unroll
    for (int i = 0; i < 4; i++) {
        int p = ty + i*8;
        float f = t[tx][p];
        __nv_bfloat16 big = __float2bfloat16(f);
        size_t o = (size_t)(b*NPIX + p0 + p)*CCH + c0 + tx;
        d_xtb[o] = big;
        d_xts[o] = __float2bfloat16(f - __bfloat162float(big));
    }
}

// ---------------- precompute: pack qkv+w weights -------------------------------
__global__ void pack_qkvw_kernel(const float* __restrict__ thw,
                                 const float* __restrict__ phw,
                                 const float* __restrict__ gw_,
                                 const float* __restrict__ ww) {
    int idx = blockIdx.x * 256 + threadIdx.x;
    const float* src;
    int off, loc, K;
    if (idx < 16384)      { src = thw; off = 0;     loc = idx;         K = 256; }
    else if (idx < 32768) { src = phw; off = 16384; loc = idx - 16384; K = 256; }
    else if (idx < 49152) { src = gw_; off = 32768; loc = idx - 32768; K = 256; }
    else                  { src = ww;  off = 49152; loc = idx - 49152; K = 128; }
    int kp = loc & (K/2 - 1);
    int m  = loc / (K/2);
    d_wpk[off + loc] = pack_bf(src[m*K + kp*2 + 1], src[m*K + kp*2]);
}

// ---------------- prep attention: transpose theta/phi bf16 -> [n][c] -----------
__global__ void prep_attn_kernel() {
    __shared__ __nv_bfloat16 t[32][34];
    int which = blockIdx.z & 1, b = blockIdx.z >> 1;
    const __nv_bfloat16* src = (which ? d_phb : d_thb) + (size_t)b*CI*NPIX;
    __nv_bfloat16* dst = (which ? d_ptb : d_ttb) + (size_t)b*NPIX*CI;
    int n0 = blockIdx.x * 32, c0 = blockIdx.y * 32;
    int tx = threadIdx.x, ty = threadIdx.y;
    #pragma unroll
    for (int i = 0; i < 4; i++)
        t[ty + i*8][tx] = src[(size_t)(c0 + ty + i*8)*NPIX + n0 + tx];
    __syncthreads();
    #pragma unroll
    for (int i = 0; i < 4; i++) {
        int n = ty + i*8;
        dst[(size_t)(n0 + n)*CI + c0 + tx] = t[tx][n];
    }
}

// ---------------- conv3x3 implicit GEMM (single-sync double buffer) -------------
#define CV_ROW 36
#define CA_PLANE (256*CV_ROW)
#define CB_PLANE (128*CV_ROW)
#define CV_STAGE (2*CA_PLANE + 2*CB_PLANE)
#define CONV_SMEM (2*CV_STAGE*4)

__global__ void __launch_bounds__(256, 1) conv_tc_kernel(const float* __restrict__ sb) {
    extern __shared__ float smem[];

    int b    = blockIdx.y;
    int pix0 = blockIdx.x * 128;
    int h0   = pix0 >> 6;

    int tid  = threadIdx.x;
    int lane = tid & 31;
    int wid  = tid >> 5;
    int wm = wid >> 1, wn = wid & 1;
    int r  = lane >> 2, cq = lane & 3;

    uint32_t base = smem_u32(smem);

    float C[32][4];
    #pragma unroll
    for (int i = 0; i < 32; i++)
        #pragma unroll
        for (int j = 0; j < 4; j++) C[i][j] = 0.f;

    auto stage = [&](int st, int kc) {
        int tap = kc >> 8;
        int c0  = kc & 255;
        int ky  = tap/3 - 1;
        int kx  = tap - (tap/3)*3 - 1;
        uint32_t sb0 = base + (uint32_t)(st*CV_STAGE*4);
        #pragma unroll
        for (int j = 0; j < 16; j++) {
            int idx = tid + j*256;
            int p   = idx >> 11;
            int rem = idx & 2047;
            int row = rem >> 3;
            int seg = rem & 7;
            const __nv_bfloat16* wsrc = (p ? d_ws : d_wb)
                + (size_t)row*KCONV + kc + seg*8;
            cp16(sb0 + (uint32_t)((p*CA_PLANE + row*CV_ROW + seg*4)*4), wsrc);
        }
        #pragma unroll
        for (int j = 0; j < 8; j++) {
            int idx = tid + j*256;
            int p   = idx >> 10;
            int rem = idx & 1023;
            int row = rem >> 3;
            int seg = rem & 7;
            int h = h0 + (row >> 6) + ky;
            int w = (row & 63) + kx;
            int valid = ((unsigned)h < 64u) & ((unsigned)w < 64u);
            int pix = valid ? (h*64 + w) : 0;
            const __nv_bfloat16* xsrc = (p ? d_xts : d_xtb)
                + (size_t)(b*NPIX + pix)*CCH + c0 + seg*8;
            cp16z(sb0 + (uint32_t)((2*CA_PLANE + p*CB_PLANE + row*CV_ROW + seg*4)*4),
                  xsrc, valid ? 16 : 0);
        }
    };

    stage(0, 0);
    cp_commit();

    for (int it = 0; it < 36; it++) {
        cp_wait<0>();
        __syncthreads();                       // single barrier per iteration
        if (it < 35) { stage((it+1) & 1, (it+1)*64); cp_commit(); }

        const float* St = smem + (it & 1)*CV_STAGE;
        const float* Ab = St;
        const float* Am = St + CA_PLANE;
        const float* Bb = St + 2*CA_PLANE;
        const float* Bm = St + 2*CA_PLANE + CB_PLANE;

        #pragma unroll
        for (int ch = 0; ch < 4; ch++) {
            int ko = ch*8 + cq;
            unsigned ab[4][4], as_[4][4];
            #pragma unroll
            for (int mt = 0; mt < 4; mt++) {
                int m = wm*64 + mt*16 + r;
                ab[mt][0] = ldu(&Ab[m*CV_ROW + ko]);
                ab[mt][1] = ldu(&Ab[(m+8)*CV_ROW + ko]);
                ab[mt][2] = ldu(&Ab[m*CV_ROW + ko + 4]);
                ab[mt][3] = ldu(&Ab[(m+8)*CV_ROW + ko + 4]);
                as_[mt][0] = ldu(&Am[m*CV_ROW + ko]);
                as_[mt][1] = ldu(&Am[(m+8)*CV_ROW + ko]);
                as_[mt][2] = ldu(&Am[m*CV_ROW + ko + 4]);
                as_[mt][3] = ldu(&Am[(m+8)*CV_ROW + ko + 4]);
            }
            unsigned bb[8][2], bs[8][2];
            #pragma unroll
            for (int nt = 0; nt < 8; nt++) {
                int n = wn*64 + nt*8 + r;
                bb[nt][0] = ldu(&Bb[n*CV_ROW + ko]);
                bb[nt][1] = ldu(&Bb[n*CV_ROW + ko + 4]);
                bs[nt][0] = ldu(&Bm[n*CV_ROW + ko]);
                bs[nt][1] = ldu(&Bm[n*CV_ROW + ko + 4]);
            }
            #pragma unroll
            for (int mt = 0; mt < 4; mt++)
                #pragma unroll
                for (int nt = 0; nt < 8; nt++)
                    mma_bf16(C[mt*8+nt], ab[mt][0], ab[mt][1], ab[mt][2], ab[mt][3],
                             bb[nt][0], bb[nt][1]);
            #pragma unroll
            for (int mt = 0; mt < 4; mt++)
                #pragma unroll
                for (int nt = 0; nt < 8; nt++)
                    mma_bf16(C[mt*8+nt], ab[mt][0], ab[mt][1], ab[mt][2], ab[mt][3],
                             bs[nt][0], bs[nt][1]);
            #pragma unroll
            for (int mt = 0; mt < 4; mt++)
                #pragma unroll
                for (int nt = 0; nt < 8; nt++)
                    mma_bf16(C[mt*8+nt], as_[mt][0], as_[mt][1], as_[mt][2], as_[mt][3],
                             bb[nt][0], bb[nt][1]);
        }
    }

    #pragma unroll
    for (int mt = 0; mt < 4; mt++) {
        int m = wm*64 + mt*16 + r;
        float bv0 = sb[m], bv8 = sb[m + 8];
        #pragma unroll
        for (int nt = 0; nt < 8; nt++) {
            int n = pix0 + wn*64 + nt*8 + 2*cq;
            float* cf = C[mt*8 + nt];
            *(float2*)&d_xs[((size_t)(b*CCH + m))*NPIX + n]     = make_float2(cf[0]+bv0, cf[1]+bv0);
            *(float2*)&d_xs[((size_t)(b*CCH + m + 8))*NPIX + n] = make_float2(cf[2]+bv8, cf[3]+bv8);
        }
    }
}

// ---------------- GroupNorm partial sums ----------------------------------------
__global__ void gn_part_kernel(int which) {
    const float* src = which ? d_z : d_xs;
    float* part      = which ? d_part2 : d_part1;
    int blk = blockIdx.x;
    int bg = blk >> 4, ch = blk & 15;
    const float4* p = (const float4*)(src + (size_t)bg*GSIZE + ch*(GSIZE/16));
    float s = 0.f, s2 = 0.f;
    #pragma unroll
    for (int i = 0; i < 8; i++) {
        float4 v = p[threadIdx.x + i*256];
        s  += v.x + v.y + v.z + v.w;
        s2 += v.x*v.x + v.y*v.y + v.z*v.z + v.w*v.w;
    }
    #pragma unroll
    for (int off = 16; off > 0; off >>= 1) {
        s  += __shfl_xor_sync(0xffffffffu, s,  off);
        s2 += __shfl_xor_sync(0xffffffffu, s2, off);
    }
    __shared__ float sh[16];
    int wid = threadIdx.x >> 5, lid = threadIdx.x & 31;
    if (lid == 0) { sh[wid] = s; sh[wid + 8] = s2; }
    __syncthreads();
    if (threadIdx.x == 0) {
        float S = 0.f, S2 = 0.f;
        #pragma unroll
        for (int w = 0; w < 8; w++) { S += sh[w]; S2 += sh[w + 8]; }
        part[blk*2]     = S;
        part[blk*2 + 1] = S2;
    }
}

// ---------------- GN1 apply + ReLU ----------------------------------------------
__global__ void gn1_apply_kernel(const float* __restrict__ gw,
                                 const float* __restrict__ gb) {
    __shared__ float st[2];
    int b  = blockIdx.z;
    int kp = blockIdx.y;
    int c  = kp << 1;
    int bg = b*8 + (kp >> 4);
    if (threadIdx.x == 0) {
        float S = 0.f, S2 = 0.f;
        #pragma unroll
        for (int i = 0; i < 16; i++) {
            S  += d_part1[(bg*16 + i)*2];
            S2 += d_part1[(bg*16 + i)*2 + 1];
        }
        float mean = S / (float)GSIZE;
        st[0] = mean;
        st[1] = rsqrtf(S2 / (float)GSIZE - mean*mean + EPSV);
    }
    __syncthreads();
    float sc0 = st[1] * gw[c],   sh0 = gb[c]   - st[0]*sc0;
    float sc1 = st[1] * gw[c+1], sh1 = gb[c+1] - st[0]*sc1;
    int n = blockIdx.x*1024 + threadIdx.x*4;
    size_t base = ((size_t)(b*CCH + c))*NPIX + n;
    float4 v0 = *(float4*)&d_xs[base];
    float4 v1 = *(float4*)&d_xs[base + NPIX];
    v0.x = fmaxf(v0.x*sc0 + sh0, 0.f); v0.y = fmaxf(v0.y*sc0 + sh0, 0.f);
    v0.z = fmaxf(v0.z*sc0 + sh0, 0.f); v0.w = fmaxf(v0.w*sc0 + sh0, 0.f);
    v1.x = fmaxf(v1.x*sc1 + sh1, 0.f); v1.y = fmaxf(v1.y*sc1 + sh1, 0.f);
    v1.z = fmaxf(v1.z*sc1 + sh1, 0.f); v1.w = fmaxf(v1.w*sc1 + sh1, 0.f);
    *(float4*)&d_xs[base]        = v0;
    *(float4*)&d_xs[base + NPIX] = v1;
    uint4 pk;
    pk.x = pack_bf(v1.x, v0.x);
    pk.y = pack_bf(v1.y, v0.y);
    pk.z = pack_bf(v1.z, v0.z);
    pk.w = pack_bf(v1.w, v0.w);
    *(uint4*)&d_xsb[((size_t)(b*128 + kp))*NPIX + n] = pk;
}

// ---------------- bf16 1x1 GEMM (single-sync) -------------------------------------
template<int MODE>
__global__ void __launch_bounds__(256) gemm_bf_kernel(const float* __restrict__ bias0,
                                                      const float* __restrict__ bias1,
                                                      const float* __restrict__ bias2) {
    constexpr int K  = (MODE == 3) ? 128 : 256;
    constexpr int KP = K / 2;
    constexpr int NI = K / 32;
    const unsigned* Wp = d_wpk + (MODE == 3 ? 49152 : 0);
    const unsigned* Xall = (MODE == 3) ? d_yb : d_xsb;

    __shared__ unsigned Ws[2][64*20];
    __shared__ unsigned Xs[2][16*132];

    int b  = blockIdx.z;
    int n0 = blockIdx.x * 128;
    int m0 = blockIdx.y * 64;
    const unsigned* Xb = Xall + (size_t)b * KP * NPIX;

    int tid  = threadIdx.x;
    int lane = tid & 31;
    int wid  = tid >> 5;
    int wm = wid >> 2, wn = wid & 3;
    int r  = lane >> 2, cq = lane & 3;

    int wRow = tid >> 2, wSeg = tid & 3;
    int xRow = tid >> 5, xSeg = tid & 31;
    uint32_t wBase = smem_u32(Ws);
    uint32_t xBase = smem_u32(Xs);

    auto stage = [&](int s, int it) {
        int kp0 = it * 16;
        cp16(wBase + (uint32_t)((s*64*20 + wRow*20 + wSeg*4)*4),
             Wp + (size_t)(m0 + wRow)*KP + kp0 + wSeg*4);
        #pragma unroll
        for (int j = 0; j < 2; j++) {
            int k = xRow + j*8;
            cp16(xBase + (uint32_t)((s*16*132 + k*132 + xSeg*4)*4),
                 Xb + (size_t)(kp0 + k)*NPIX + n0 + xSeg*4);
        }
    };

    float C[8][4];
    #pragma unroll
    for (int i = 0; i < 8; i++)
        #pragma unroll
        for (int j = 0; j < 4; j++) C[i][j] = 0.f;

    stage(0, 0);
    cp_commit();

    for (int it = 0; it < NI; it++) {
        cp_wait<0>();
        __syncthreads();
        if (it < NI-1) { stage((it+1)&1, it+1); cp_commit(); }

        const unsigned* Wt = Ws[it & 1];
        const unsigned* Xt = Xs[it & 1];

        #pragma unroll
        for (int ch = 0; ch < 2; ch++) {
            int ko = ch*8 + cq;
            unsigned a[2][4];
            #pragma unroll
            for (int mt = 0; mt < 2; mt++) {
                int mr = wm*32 + mt*16 + r;
                a[mt][0] = Wt[mr*20 + ko];
                a[mt][1] = Wt[(mr+8)*20 + ko];
                a[mt][2] = Wt[mr*20 + ko + 4];
                a[mt][3] = Wt[(mr+8)*20 + ko + 4];
            }
            #pragma unroll
            for (int nt = 0; nt < 4; nt++) {
                int nn = wn*32 + nt*8 + r;
                unsigned b0 = Xt[ko*132 + nn];
                unsigned b1 = Xt[(ko+4)*132 + nn];
                mma_bf16(C[nt],     a[0][0], a[0][1], a[0][2], a[0][3], b0, b1);
                mma_bf16(C[4 + nt], a[1][0], a[1][1], a[1][2], a[1][3], b0, b1);
            }
        }
    }

    const float* bias = (MODE == 3) ? bias0
                      : (m0 < 128 ? bias0 : m0 < 256 ? bias1 : bias2);
    int mbase = (MODE == 3) ? m0 : (m0 & 127);
    __nv_bfloat16* Obf = nullptr;
    if (MODE != 3)
        Obf = (m0 < 128 ? d_thb : m0 < 256 ? d_phb : d_gb) + (size_t)b * CI * NPIX;

    #pragma unroll
    for (int mt = 0; mt < 2; mt++) {
        int ml = mbase + wm*32 + mt*16 + r;
        float bv0 = bias[ml], bv8 = bias[ml + 8];
        #pragma unroll
        for (int nt = 0; nt < 4; nt++) {
            int n = n0 + wn*32 + nt*8 + 2*cq;
            float* cf = C[mt*4 + nt];
            if (MODE == 3) {
                float* Ob = d_z + (size_t)b * CCH * NPIX;
                *(float2*)&Ob[(size_t)ml*NPIX + n]     = make_float2(cf[0]+bv0, cf[1]+bv0);
                *(float2*)&Ob[(size_t)(ml+8)*NPIX + n] = make_float2(cf[2]+bv8, cf[3]+bv8);
            } else {
                *(unsigned*)&Obf[(size_t)ml*NPIX + n]     = pack_bf(cf[1]+bv0, cf[0]+bv0);
                *(unsigned*)&Obf[(size_t)(ml+8)*NPIX + n] = pack_bf(cf[3]+bv8, cf[2]+bv8);
            }
        }
    }
}

// ---------------- bf16 flash attention: single sync per tile ---------------------
#define KS_STR 68
#define KS_STAGE (64*KS_STR)
#define GS_STR 36
#define GS_STAGE (128*GS_STR)
#define ATTN_SMEM ((2*KS_STAGE + 2*GS_STAGE)*4)

__global__ void __launch_bounds__(128, 2) attention_tc_kernel() {
    extern __shared__ float smem[];
    float* sK = smem;
    float* sG = smem + 2*KS_STAGE;

    int b  = blockIdx.y;
    int n0 = blockIdx.x * 64;
    const __nv_bfloat16* Tt = d_ttb + (size_t)b * NPIX * CI;
    const __nv_bfloat16* Pt = d_ptb + (size_t)b * NPIX * CI;
    const __nv_bfloat16* Gp = d_gb  + (size_t)b * CI * NPIX;
    unsigned* Ybu = d_yb + (size_t)b * 64 * NPIX;

    int tid  = threadIdx.x;
    int lane = tid & 31;
    int wid  = tid >> 5;
    int qb   = wid * 16;
    int r    = lane >> 2;
    int cq   = lane & 3;

    uint32_t kBase = smem_u32(sK);
    uint32_t gBase = smem_u32(sG);

    auto stageK = [&](int s, int m0k) {
        #pragma unroll
        for (int j = 0; j < 8; j++) {
            int idx = tid + j*128;
            int row = idx >> 4, seg = idx & 15;
            cp16(kBase + (uint32_t)((s*KS_STAGE + row*KS_STR + seg*4)*4),
                 Pt + (size_t)(m0k + row)*CI + seg*8);
        }
    };
    auto stageG = [&](int s, int m0k) {
        #pragma unroll
        for (int j = 0; j < 8; j++) {
            int idx = tid + j*128;
            int row = idx >> 3, seg = idx & 7;
            cp16(gBase + (uint32_t)((s*GS_STAGE + row*GS_STR + seg*4)*4),
                 Gp + (size_t)row*NPIX + m0k + seg*8);
        }
    };

    // ---- Q prologue ----
    #pragma unroll
    for (int j = 0; j < 8; j++) {
        int idx = tid + j*128;
        int row = idx >> 4, seg = idx & 15;
        cp16(kBase + (uint32_t)((row*KS_STR + seg*4)*4),
             Tt + (size_t)(n0 + row)*CI + seg*8);
    }
    cp_commit();
    cp_wait<0>();
    __syncthreads();

    unsigned qa[8][4];
    #pragma unroll
    for (int ch = 0; ch < 8; ch++) {
        int ko = ch*8 + cq;
        qa[ch][0] = ldu(&sK[(qb + r)*KS_STR + ko]);
        qa[ch][1] = ldu(&sK[(qb + r + 8)*KS_STR + ko]);
        qa[ch][2] = ldu(&sK[(qb + r)*KS_STR + ko + 4]);
        qa[ch][3] = ldu(&sK[(qb + r + 8)*KS_STR + ko + 4]);
    }
    __syncthreads();

    stageK(0, 0);
    stageG(0, 0);
    cp_commit();

    float O[16][4];
    #pragma unroll
    for (int i = 0; i < 16; i++)
        #pragma unroll
        for (int j = 0; j < 4; j++) O[i][j] = 0.f;
    float Mx0 = -1e30f, Mx1 = -1e30f, L0 = 0.f, L1 = 0.f;
    const unsigned FULL = 0xffffffffu;

    for (int t = 0; t < 64; t++) {
        int s = t & 1;
        int m0 = t * 64;

        cp_wait<0>();
        __syncthreads();                      // single barrier per tile
        if (t < 63) {
            stageK(s^1, m0 + 64);
            stageG(s^1, m0 + 64);
            cp_commit();
        }

        const float* Kt = sK + s*KS_STAGE;
        float S[8][4];
        #pragma unroll
        for (int i = 0; i < 8; i++)
            #pragma unroll
            for (int j = 0; j < 4; j++) S[i][j] = 0.f;

        #pragma unroll
        for (int ch = 0; ch < 8; ch++) {
            int ko = ch*8 + cq;
            #pragma unroll
            for (int nt = 0; nt < 8; nt++) {
                unsigned b0 = ldu(&Kt[(nt*8 + r)*KS_STR + ko]);
                unsigned b1 = ldu(&Kt[(nt*8 + r)*KS_STR + ko + 4]);
                mma_bf16(S[nt], qa[ch][0], qa[ch][1], qa[ch][2], qa[ch][3], b0, b1);
            }
        }

        float rm0 = -1e30f, rm1 = -1e30f;
        #pragma unroll
        for (int nt = 0; nt < 8; nt++) {
            rm0 = fmaxf(rm0, fmaxf(S[nt][0], S[nt][1]));
            rm1 = fmaxf(rm1, fmaxf(S[nt][2], S[nt][3]));
        }
        rm0 = fmaxf(rm0, __shfl_xor_sync(FULL, rm0, 1));
        rm0 = fmaxf(rm0, __shfl_xor_sync(FULL, rm0, 2));
        rm1 = fmaxf(rm1, __shfl_xor_sync(FULL, rm1, 1));
        rm1 = fmaxf(rm1, __shfl_xor_sync(FULL, rm1, 2));

        float nm0 = fmaxf(Mx0, rm0), nm1 = fmaxf(Mx1, rm1);
        float sc0 = __expf(Mx0 - nm0), sc1 = __expf(Mx1 - nm1);
        Mx0 = nm0; Mx1 = nm1;

        float rs0 = 0.f, rs1 = 0.f;
        #pragma unroll
        for (int nt = 0; nt < 8; nt++) {
            S[nt][0] = __expf(S[nt][0] - nm0);
            S[nt][1] = __expf(S[nt][1] - nm0);
            S[nt][2] = __expf(S[nt][2] - nm1);
            S[nt][3] = __expf(S[nt][3] - nm1);
            rs0 += S[nt][0] + S[nt][1];
            rs1 += S[nt][2] + S[nt][3];
        }
        rs0 += __shfl_xor_sync(FULL, rs0, 1);
        rs0 += __shfl_xor_sync(FULL, rs0, 2);
        rs1 += __shfl_xor_sync(FULL, rs1, 1);
        rs1 += __shfl_xor_sync(FULL, rs1, 2);
        L0 = L0*sc0 + rs0;
        L1 = L1*sc1 + rs1;

        if (!__all_sync(FULL, (sc0 == 1.f) & (sc1 == 1.f))) {
            #pragma unroll
            for (int i = 0; i < 16; i++) {
                O[i][0] *= sc0; O[i][1] *= sc0;
                O[i][2] *= sc1; O[i][3] *= sc1;
            }
        }

        unsigned pa[4][4];
        #pragma unroll
        for (int kc = 0; kc < 4; kc++) {
            pa[kc][0] = pack_bf(S[2*kc][1],   S[2*kc][0]);
            pa[kc][1] = pack_bf(S[2*kc][3],   S[2*kc][2]);
            pa[kc][2] = pack_bf(S[2*kc+1][1], S[2*kc+1][0]);
            pa[kc][3] = pack_bf(S[2*kc+1][3], S[2*kc+1][2]);
        }

        const float* Gt = sG + s*GS_STAGE;
        #pragma unroll
        for (int kc = 0; kc < 4; kc++) {
            int ko = kc*8 + cq;
            #pragma unroll
            for (int ct = 0; ct < 16; ct++) {
                unsigned b0 = ldu(&Gt[(ct*8 + r)*GS_STR + ko]);
                unsigned b1 = ldu(&Gt[(ct*8 + r)*GS_STR + ko + 4]);
                mma_bf16(O[ct], pa[kc][0], pa[kc][1], pa[kc][2], pa[kc][3], b0, b1);
            }
        }
    }

    float inv0 = 1.0f / L0, inv1 = 1.0f / L1;
    int q = n0 + qb + r;
    #pragma unroll
    for (int ct = 0; ct < 16; ct++) {
        int kp = ct*4 + cq;
        Ybu[(size_t)kp*NPIX + q]     = pack_bf(O[ct][1]*inv0, O[ct][0]*inv0);
        Ybu[(size_t)kp*NPIX + q + 8] = pack_bf(O[ct][3]*inv1, O[ct][2]*inv1);
    }
}

// ---------------- final: out = GN2(z)*0.1 + xs ------------------------------------
__global__ void final_apply_kernel(const float* __restrict__ gw,
                                   const float* __restrict__ gb,
                                   float* __restrict__ out) {
    __shared__ float st[2];
    int bg = blockIdx.x >> 7;
    if (threadIdx.x == 0) {
        float S = 0.f, S2 = 0.f;
        #pragma unroll
        for (int i = 0; i < 16; i++) {
            S  += d_part2[(bg*16 + i)*2];
            S2 += d_part2[(bg*16 + i)*2 + 1];
        }
        float mean = S / (float)GSIZE;
        st[0] = mean;
        st[1] = rsqrtf(S2 / (float)GSIZE - mean*mean + EPSV);
    }
    __syncthreads();
    int i4 = blockIdx.x * blockDim.x + threadIdx.x;
    int idx = i4 << 2;
    int c   = (idx >> 12) & 255;
    float sc = st[1] * gw[c];
    float sh = gb[c] - st[0] * sc;
    float4 z = ((const float4*)d_z)[i4];
    float4 xs = ((const float4*)d_xs)[i4];
    float4 o;
    o.x = (z.x*sc + sh)*0.1f + xs.x;
    o.y = (z.y*sc + sh)*0.1f + xs.y;
    o.z = (z.z*sc + sh)*0.1f + xs.z;
    o.w = (z.w*sc + sh)*0.1f + xs.w;
    ((float4*)out)[i4] = o;
}

// ---------------- launch -----------------------------------------------------------
extern "C" void kernel_launch(void* const* d_in, const int* in_sizes, int n_in,
                              void* d_out, int out_size) {
    const float* x    = (const float*)d_in[0];
    const float* sw   = (const float*)d_in[1];
    const float* sb   = (const float*)d_in[2];
    const float* gn1w = (const float*)d_in[3];
    const float* gn1b = (const float*)d_in[4];
    const float* g_w  = (const float*)d_in[5];
    const float* g_b  = (const float*)d_in[6];
    const float* th_w = (const float*)d_in[7];
    const float* th_b = (const float*)d_in[8];
    const float* ph_w = (const float*)d_in[9];
    const float* ph_b = (const float*)d_in[10];
    const float* w_w  = (const float*)d_in[11];
    const float* w_b  = (const float*)d_in[12];
    const float* gn2w = (const float*)d_in[13];
    const float* gn2b = (const float*)d_in[14];
    float* out = (float*)d_out;

    static int attrSet = 0;
    if (!attrSet) {
        cudaFuncSetAttribute(conv_tc_kernel,
                             cudaFuncAttributeMaxDynamicSharedMemorySize, CONV_SMEM);
        cudaFuncSetAttribute(attention_tc_kernel,
                             cudaFuncAttributeMaxDynamicSharedMemorySize, ATTN_SMEM);
        attrSet = 1;
    }

    pack_w_bf_kernel<<<dim3(9, 256), 256>>>(sw);
    prep_x_kernel<<<dim3(128, 8, 4), dim3(32, 8)>>>(x);
    pack_qkvw_kernel<<<256, 256>>>(th_w, ph_w, g_w, w_w);
    conv_tc_kernel<<<dim3(32, 4), 256, CONV_SMEM>>>(sb);
    gn_part_kernel<<<512, 256>>>(0);
    gn1_apply_kernel<<<dim3(4, 128, 4), 256>>>(gn1w, gn1b);

    gemm_bf_kernel<0><<<dim3(32, 6, 4), 256>>>(th_b, ph_b, g_b);
    prep_attn_kernel<<<dim3(128, 4, 8), dim3(32, 8)>>>();

    attention_tc_kernel<<<dim3(64, 4), 128, ATTN_SMEM>>>();

    gemm_bf_kernel<3><<<dim3(32, 4, 4), 256>>>(w_b, nullptr, nullptr);
    gn_part_kernel<<<512, 256>>>(1);
    final_apply_kernel<<<4096, 256>>>(gn2w, gn2b, out);

    (void)in_sizes; (void)n_in; (void)out_size;
}

// round 15
// speedup vs baseline: 1.0207x; 1.0207x over previous
#include <cuda_runtime.h>
#include <cuda_bf16.h>
#include <math.h>
#include <stdint.h>

#define BATCH 4
#define CCH   256
#define CI    128
#define NPIX  4096
#define GROUPS 8
#define CPG   32
#define GSIZE (CPG*NPIX)
#define EPSV  1e-5f
#define KCONV 2304

// ---------------- scratch ----------------------------------------------------
__device__ float d_xs   [BATCH*CCH*NPIX];
__device__ float d_z    [BATCH*CCH*NPIX];
__device__ unsigned d_xsb[BATCH*128*NPIX];
__device__ unsigned d_yb [BATCH*64*NPIX];
__device__ unsigned d_wpk[65536];
__device__ __nv_bfloat16 d_wb [CCH*KCONV];
__device__ __nv_bfloat16 d_ws [CCH*KCONV];
__device__ __nv_bfloat16 d_xtb[BATCH*NPIX*CCH];
__device__ __nv_bfloat16 d_xts[BATCH*NPIX*CCH];
__device__ __nv_bfloat16 d_thb[BATCH*CI*NPIX];
__device__ __nv_bfloat16 d_phb[BATCH*CI*NPIX];
__device__ __nv_bfloat16 d_ttb[BATCH*NPIX*CI];
__device__ __nv_bfloat16 d_ptb[BATCH*NPIX*CI];
__device__ __nv_bfloat16 d_gb [BATCH*CI*NPIX];
__device__ float d_part1[64];     // [b*8+g][2] totals (atomic)
__device__ float d_part2[64];

// ---------------- helpers -----------------------------------------------------
__device__ __forceinline__ void mma_bf16(float* c,
    unsigned a0, unsigned a1, unsigned a2, unsigned a3,
    unsigned b0, unsigned b1) {
    asm volatile(
        "mma.sync.aligned.m16n8k16.row.col.f32.bf16.bf16.f32 "
        "{%0,%1,%2,%3}, {%4,%5,%6,%7}, {%8,%9}, {%0,%1,%2,%3};"
        : "+f"(c[0]), "+f"(c[1]), "+f"(c[2]), "+f"(c[3])
        : "r"(a0), "r"(a1), "r"(a2), "r"(a3), "r"(b0), "r"(b1));
}
__device__ __forceinline__ unsigned pack_bf(float hi, float lo) {
    unsigned u;
    asm("cvt.rn.bf16x2.f32 %0, %1, %2;" : "=r"(u) : "f"(hi), "f"(lo));
    return u;
}
__device__ __forceinline__ void cp16(uint32_t dst, const void* src) {
    asm volatile("cp.async.cg.shared.global [%0], [%1], 16;" :: "r"(dst), "l"(src));
}
__device__ __forceinline__ void cp16z(uint32_t dst, const void* src, int srcsz) {
    asm volatile("cp.async.cg.shared.global [%0], [%1], 16, %2;"
                 :: "r"(dst), "l"(src), "r"(srcsz));
}
__device__ __forceinline__ void cp_commit() {
    asm volatile("cp.async.commit_group;");
}
template<int N>
__device__ __forceinline__ void cp_wait() {
    asm volatile("cp.async.wait_group %0;" :: "n"(N));
}
__device__ __forceinline__ uint32_t smem_u32(const void* p) {
    return (uint32_t)__cvta_generic_to_shared(p);
}
__device__ __forceinline__ unsigned ldu(const float* p) {
    return __float_as_uint(*p);
}
__device__ __forceinline__ void wred2(float& s, float& s2) {
    #pragma unroll
    for (int off = 16; off > 0; off >>= 1) {
        s  += __shfl_xor_sync(0xffffffffu, s,  off);
        s2 += __shfl_xor_sync(0xffffffffu, s2, off);
    }
}

// ---------------- precompute: conv weight 2-term bf16 split --------------------
__global__ void pack_w_bf_kernel(const float* __restrict__ w) {
    int k = blockIdx.x * 256 + threadIdx.x;
    int m = blockIdx.y;
    int c = k & 255, tap = k >> 8;
    float f = w[m*(CCH*9) + c*9 + tap];
    __nv_bfloat16 big = __float2bfloat16(f);
    d_wb[(size_t)m*KCONV + k] = big;
    d_ws[(size_t)m*KCONV + k] = __float2bfloat16(f - __bfloat162float(big));
}

// ---------------- precompute: x transpose + split -> [b][pix][c] bf16 ---------
__global__ void prep_x_kernel(const float* __restrict__ x) {
    __shared__ float t[32][33];
    int b  = blockIdx.z;
    int p0 = blockIdx.x * 32;
    int c0 = blockIdx.y * 32;
    int tx = threadIdx.x, ty = threadIdx.y;
    #pragma unroll
    for (int i = 0; i < 4; i++)
        t[ty + i*8][tx] = x[(size_t)(b*CCH + c0 + ty + i*8)*NPIX + p0 + tx];
    __syncthreads();
    #pragma unroll
    for (int i = 0; i < 4; i++) {
        int p = ty + i*8;
        float f = t[tx][p];
        __nv_bfloat16 big = __float2bfloat16(f);
        size_t o = (size_t)(b*NPIX + p0 + p)*CCH + c0 + tx;
        d_xtb[o] = big;
        d_xts[o] = __float2bfloat16(f - __bfloat162float(big));
    }
}

// ---------------- precompute: pack qkv+w weights + zero stats -------------------
__global__ void pack_qkvw_kernel(const float* __restrict__ thw,
                                 const float* __restrict__ phw,
                                 const float* __restrict__ gw_,
                                 const float* __restrict__ ww) {
    int idx = blockIdx.x * 256 + threadIdx.x;
    if (idx < 64)  d_part1[idx] = 0.f;
    else if (idx < 128) d_part2[idx - 64] = 0.f;
    const float* src;
    int off, loc, K;
    if (idx < 16384)      { src = thw; off = 0;     loc = idx;         K = 256; }
    else if (idx < 32768) { src = phw; off = 16384; loc = idx - 16384; K = 256; }
    else if (idx < 49152) { src = gw_; off = 32768; loc = idx - 32768; K = 256; }
    else                  { src = ww;  off = 49152; loc = idx - 49152; K = 128; }
    int kp = loc & (K/2 - 1);
    int m  = loc / (K/2);
    d_wpk[off + loc] = pack_bf(src[m*K + kp*2 + 1], src[m*K + kp*2]);
}

// ---------------- prep attention: transpose theta/phi bf16 -> [n][c] -----------
__global__ void prep_attn_kernel() {
    __shared__ __nv_bfloat16 t[32][34];
    int which = blockIdx.z & 1, b = blockIdx.z >> 1;
    const __nv_bfloat16* src = (which ? d_phb : d_thb) + (size_t)b*CI*NPIX;
    __nv_bfloat16* dst = (which ? d_ptb : d_ttb) + (size_t)b*NPIX*CI;
    int n0 = blockIdx.x * 32, c0 = blockIdx.y * 32;
    int tx = threadIdx.x, ty = threadIdx.y;
    #pragma unroll
    for (int i = 0; i < 4; i++)
        t[ty + i*8][tx] = src[(size_t)(c0 + ty + i*8)*NPIX + n0 + tx];
    __syncthreads();
    #pragma unroll
    for (int i = 0; i < 4; i++) {
        int n = ty + i*8;
        dst[(size_t)(n0 + n)*CI + c0 + tx] = t[tx][n];
    }
}

// ---------------- conv3x3 implicit GEMM (R13 two-sync; fused GN1 stats) ---------
#define CV_ROW 36
#define CA_PLANE (256*CV_ROW)
#define CB_PLANE (128*CV_ROW)
#define CV_STAGE (2*CA_PLANE + 2*CB_PLANE)
#define CONV_SMEM (2*CV_STAGE*4)

__global__ void __launch_bounds__(256, 1) conv_tc_kernel(const float* __restrict__ sb) {
    extern __shared__ float smem[];

    int b    = blockIdx.y;
    int pix0 = blockIdx.x * 128;
    int h0   = pix0 >> 6;

    int tid  = threadIdx.x;
    int lane = tid & 31;
    int wid  = tid >> 5;
    int wm = wid >> 1, wn = wid & 1;
    int r  = lane >> 2, cq = lane & 3;

    uint32_t base = smem_u32(smem);

    float C[32][4];
    #pragma unroll
    for (int i = 0; i < 32; i++)
        #pragma unroll
        for (int j = 0; j < 4; j++) C[i][j] = 0.f;

    auto stage = [&](int st, int kc) {
        int tap = kc >> 8;
        int c0  = kc & 255;
        int ky  = tap/3 - 1;
        int kx  = tap - (tap/3)*3 - 1;
        uint32_t sb0 = base + (uint32_t)(st*CV_STAGE*4);
        #pragma unroll
        for (int j = 0; j < 16; j++) {
            int idx = tid + j*256;
            int p   = idx >> 11;
            int rem = idx & 2047;
            int row = rem >> 3;
            int seg = rem & 7;
            const __nv_bfloat16* wsrc = (p ? d_ws : d_wb)
                + (size_t)row*KCONV + kc + seg*8;
            cp16(sb0 + (uint32_t)((p*CA_PLANE + row*CV_ROW + seg*4)*4), wsrc);
        }
        #pragma unroll
        for (int j = 0; j < 8; j++) {
            int idx = tid + j*256;
            int p   = idx >> 10;
            int rem = idx & 1023;
            int row = rem >> 3;
            int seg = rem & 7;
            int h = h0 + (row >> 6) + ky;
            int w = (row & 63) + kx;
            int valid = ((unsigned)h < 64u) & ((unsigned)w < 64u);
            int pix = valid ? (h*64 + w) : 0;
            const __nv_bfloat16* xsrc = (p ? d_xts : d_xtb)
                + (size_t)(b*NPIX + pix)*CCH + c0 + seg*8;
            cp16z(sb0 + (uint32_t)((2*CA_PLANE + p*CB_PLANE + row*CV_ROW + seg*4)*4),
                  xsrc, valid ? 16 : 0);
        }
    };

    stage(0, 0);
    cp_commit();

    for (int it = 0; it < 36; it++) {
        if (it < 35) { stage((it+1) & 1, (it+1)*64); cp_commit(); cp_wait<1>(); }
        else cp_wait<0>();
        __syncthreads();

        const float* St = smem + (it & 1)*CV_STAGE;
        const float* Ab = St;
        const float* Am = St + CA_PLANE;
        const float* Bb = St + 2*CA_PLANE;
        const float* Bm = St + 2*CA_PLANE + CB_PLANE;

        #pragma unroll
        for (int ch = 0; ch < 4; ch++) {
            int ko = ch*8 + cq;
            unsigned ab[4][4], as_[4][4];
            #pragma unroll
            for (int mt = 0; mt < 4; mt++) {
                int m = wm*64 + mt*16 + r;
                ab[mt][0] = ldu(&Ab[m*CV_ROW + ko]);
                ab[mt][1] = ldu(&Ab[(m+8)*CV_ROW + ko]);
                ab[mt][2] = ldu(&Ab[m*CV_ROW + ko + 4]);
                ab[mt][3] = ldu(&Ab[(m+8)*CV_ROW + ko + 4]);
                as_[mt][0] = ldu(&Am[m*CV_ROW + ko]);
                as_[mt][1] = ldu(&Am[(m+8)*CV_ROW + ko]);
                as_[mt][2] = ldu(&Am[m*CV_ROW + ko + 4]);
                as_[mt][3] = ldu(&Am[(m+8)*CV_ROW + ko + 4]);
            }
            unsigned bb[8][2], bs[8][2];
            #pragma unroll
            for (int nt = 0; nt < 8; nt++) {
                int n = wn*64 + nt*8 + r;
                bb[nt][0] = ldu(&Bb[n*CV_ROW + ko]);
                bb[nt][1] = ldu(&Bb[n*CV_ROW + ko + 4]);
                bs[nt][0] = ldu(&Bm[n*CV_ROW + ko]);
                bs[nt][1] = ldu(&Bm[n*CV_ROW + ko + 4]);
            }
            #pragma unroll
            for (int mt = 0; mt < 4; mt++)
                #pragma unroll
                for (int nt = 0; nt < 8; nt++)
                    mma_bf16(C[mt*8+nt], ab[mt][0], ab[mt][1], ab[mt][2], ab[mt][3],
                             bb[nt][0], bb[nt][1]);
            #pragma unroll
            for (int mt = 0; mt < 4; mt++)
                #pragma unroll
                for (int nt = 0; nt < 8; nt++)
                    mma_bf16(C[mt*8+nt], ab[mt][0], ab[mt][1], ab[mt][2], ab[mt][3],
                             bs[nt][0], bs[nt][1]);
            #pragma unroll
            for (int mt = 0; mt < 4; mt++)
                #pragma unroll
                for (int nt = 0; nt < 8; nt++)
                    mma_bf16(C[mt*8+nt], as_[mt][0], as_[mt][1], as_[mt][2], as_[mt][3],
                             bb[nt][0], bb[nt][1]);
        }
        __syncthreads();
    }

    // epilogue: store + fused GN1 partial stats (group is warp-uniform per mt)
    #pragma unroll
    for (int mt = 0; mt < 4; mt++) {
        int m = wm*64 + mt*16 + r;
        float bv0 = sb[m], bv8 = sb[m + 8];
        float s = 0.f, s2 = 0.f;
        #pragma unroll
        for (int nt = 0; nt < 8; nt++) {
            int n = pix0 + wn*64 + nt*8 + 2*cq;
            float* cf = C[mt*8 + nt];
            float v0 = cf[0]+bv0, v1 = cf[1]+bv0, v2 = cf[2]+bv8, v3 = cf[3]+bv8;
            *(float2*)&d_xs[((size_t)(b*CCH + m))*NPIX + n]     = make_float2(v0, v1);
            *(float2*)&d_xs[((size_t)(b*CCH + m + 8))*NPIX + n] = make_float2(v2, v3);
            s  += v0 + v1 + v2 + v3;
            s2 += v0*v0 + v1*v1 + v2*v2 + v3*v3;
        }
        wred2(s, s2);
        if (lane == 0) {
            int bg = b*8 + wm*2 + (mt >> 1);
            atomicAdd(&d_part1[bg*2],     s);
            atomicAdd(&d_part1[bg*2 + 1], s2);
        }
    }
}

// ---------------- GN1 apply + ReLU (totals read directly) ------------------------
__global__ void gn1_apply_kernel(const float* __restrict__ gw,
                                 const float* __restrict__ gb) {
    __shared__ float st[2];
    int b  = blockIdx.z;
    int kp = blockIdx.y;
    int c  = kp << 1;
    int bg = b*8 + (kp >> 4);
    if (threadIdx.x == 0) {
        float S  = d_part1[bg*2];
        float S2 = d_part1[bg*2 + 1];
        float mean = S / (float)GSIZE;
        st[0] = mean;
        st[1] = rsqrtf(S2 / (float)GSIZE - mean*mean + EPSV);
    }
    __syncthreads();
    float sc0 = st[1] * gw[c],   sh0 = gb[c]   - st[0]*sc0;
    float sc1 = st[1] * gw[c+1], sh1 = gb[c+1] - st[0]*sc1;
    int n = blockIdx.x*1024 + threadIdx.x*4;
    size_t base = ((size_t)(b*CCH + c))*NPIX + n;
    float4 v0 = *(float4*)&d_xs[base];
    float4 v1 = *(float4*)&d_xs[base + NPIX];
    v0.x = fmaxf(v0.x*sc0 + sh0, 0.f); v0.y = fmaxf(v0.y*sc0 + sh0, 0.f);
    v0.z = fmaxf(v0.z*sc0 + sh0, 0.f); v0.w = fmaxf(v0.w*sc0 + sh0, 0.f);
    v1.x = fmaxf(v1.x*sc1 + sh1, 0.f); v1.y = fmaxf(v1.y*sc1 + sh1, 0.f);
    v1.z = fmaxf(v1.z*sc1 + sh1, 0.f); v1.w = fmaxf(v1.w*sc1 + sh1, 0.f);
    *(float4*)&d_xs[base]        = v0;
    *(float4*)&d_xs[base + NPIX] = v1;
    uint4 pk;
    pk.x = pack_bf(v1.x, v0.x);
    pk.y = pack_bf(v1.y, v0.y);
    pk.z = pack_bf(v1.z, v0.z);
    pk.w = pack_bf(v1.w, v0.w);
    *(uint4*)&d_xsb[((size_t)(b*128 + kp))*NPIX + n] = pk;
}

// ---------------- bf16 1x1 GEMM (MODE 3 fuses GN2 stats) --------------------------
template<int MODE>
__global__ void __launch_bounds__(256) gemm_bf_kernel(const float* __restrict__ bias0,
                                                      const float* __restrict__ bias1,
                                                      const float* __restrict__ bias2) {
    constexpr int K  = (MODE == 3) ? 128 : 256;
    constexpr int KP = K / 2;
    constexpr int NI = K / 32;
    const unsigned* Wp = d_wpk + (MODE == 3 ? 49152 : 0);
    const unsigned* Xall = (MODE == 3) ? d_yb : d_xsb;

    __shared__ unsigned Ws[2][64*20];
    __shared__ unsigned Xs[2][16*132];

    int b  = blockIdx.z;
    int n0 = blockIdx.x * 128;
    int m0 = blockIdx.y * 64;
    const unsigned* Xb = Xall + (size_t)b * KP * NPIX;

    int tid  = threadIdx.x;
    int lane = tid & 31;
    int wid  = tid >> 5;
    int wm = wid >> 2, wn = wid & 3;
    int r  = lane >> 2, cq = lane & 3;

    int wRow = tid >> 2, wSeg = tid & 3;
    int xRow = tid >> 5, xSeg = tid & 31;
    uint32_t wBase = smem_u32(Ws);
    uint32_t xBase = smem_u32(Xs);

    auto stage = [&](int s, int it) {
        int kp0 = it * 16;
        cp16(wBase + (uint32_t)((s*64*20 + wRow*20 + wSeg*4)*4),
             Wp + (size_t)(m0 + wRow)*KP + kp0 + wSeg*4);
        #pragma unroll
        for (int j = 0; j < 2; j++) {
            int k = xRow + j*8;
            cp16(xBase + (uint32_t)((s*16*132 + k*132 + xSeg*4)*4),
                 Xb + (size_t)(kp0 + k)*NPIX + n0 + xSeg*4);
        }
    };

    float C[8][4];
    #pragma unroll
    for (int i = 0; i < 8; i++)
        #pragma unroll
        for (int j = 0; j < 4; j++) C[i][j] = 0.f;

    stage(0, 0);
    cp_commit();

    for (int it = 0; it < NI; it++) {
        if (it < NI-1) { stage((it+1)&1, it+1); cp_commit(); cp_wait<1>(); }
        else cp_wait<0>();
        __syncthreads();

        const unsigned* Wt = Ws[it & 1];
        const unsigned* Xt = Xs[it & 1];

        #pragma unroll
        for (int ch = 0; ch < 2; ch++) {
            int ko = ch*8 + cq;
            unsigned a[2][4];
            #pragma unroll
            for (int mt = 0; mt < 2; mt++) {
                int mr = wm*32 + mt*16 + r;
                a[mt][0] = Wt[mr*20 + ko];
                a[mt][1] = Wt[(mr+8)*20 + ko];
                a[mt][2] = Wt[mr*20 + ko + 4];
                a[mt][3] = Wt[(mr+8)*20 + ko + 4];
            }
            #pragma unroll
            for (int nt = 0; nt < 4; nt++) {
                int nn = wn*32 + nt*8 + r;
                unsigned b0 = Xt[ko*132 + nn];
                unsigned b1 = Xt[(ko+4)*132 + nn];
                mma_bf16(C[nt],     a[0][0], a[0][1], a[0][2], a[0][3], b0, b1);
                mma_bf16(C[4 + nt], a[1][0], a[1][1], a[1][2], a[1][3], b0, b1);
            }
        }
        __syncthreads();
    }

    const float* bias = (MODE == 3) ? bias0
                      : (m0 < 128 ? bias0 : m0 < 256 ? bias1 : bias2);
    int mbase = (MODE == 3) ? m0 : (m0 & 127);
    __nv_bfloat16* Obf = nullptr;
    if (MODE != 3)
        Obf = (m0 < 128 ? d_thb : m0 < 256 ? d_phb : d_gb) + (size_t)b * CI * NPIX;

    float s = 0.f, s2 = 0.f;
    #pragma unroll
    for (int mt = 0; mt < 2; mt++) {
        int ml = mbase + wm*32 + mt*16 + r;
        float bv0 = bias[ml], bv8 = bias[ml + 8];
        #pragma unroll
        for (int nt = 0; nt < 4; nt++) {
            int n = n0 + wn*32 + nt*8 + 2*cq;
            float* cf = C[mt*4 + nt];
            if (MODE == 3) {
                float v0 = cf[0]+bv0, v1 = cf[1]+bv0, v2 = cf[2]+bv8, v3 = cf[3]+bv8;
                float* Ob = d_z + (size_t)b * CCH * NPIX;
                *(float2*)&Ob[(size_t)ml*NPIX + n]     = make_float2(v0, v1);
                *(float2*)&Ob[(size_t)(ml+8)*NPIX + n] = make_float2(v2, v3);
                s  += v0 + v1 + v2 + v3;
                s2 += v0*v0 + v1*v1 + v2*v2 + v3*v3;
            } else {
                *(unsigned*)&Obf[(size_t)ml*NPIX + n]     = pack_bf(cf[1]+bv0, cf[0]+bv0);
                *(unsigned*)&Obf[(size_t)(ml+8)*NPIX + n] = pack_bf(cf[3]+bv8, cf[2]+bv8);
            }
        }
    }
    if (MODE == 3) {
        wred2(s, s2);   // group = (m0>>5)+wm is warp-uniform
        if (lane == 0) {
            int bg = b*8 + (m0 >> 5) + wm;
            atomicAdd(&d_part2[bg*2],     s);
            atomicAdd(&d_part2[bg*2 + 1], s2);
        }
    }
}

// ---------------- bf16 flash attention (R13 version) ------------------------------
#define KS_STR 68
#define KS_STAGE (64*KS_STR)
#define GS_STR 36
#define GS_STAGE (128*GS_STR)
#define ATTN_SMEM ((2*KS_STAGE + 2*GS_STAGE)*4)

__global__ void __launch_bounds__(128, 2) attention_tc_kernel() {
    extern __shared__ float smem[];
    float* sK = smem;
    float* sG = smem + 2*KS_STAGE;

    int b  = blockIdx.y;
    int n0 = blockIdx.x * 64;
    const __nv_bfloat16* Tt = d_ttb + (size_t)b * NPIX * CI;
    const __nv_bfloat16* Pt = d_ptb + (size_t)b * NPIX * CI;
    const __nv_bfloat16* Gp = d_gb  + (size_t)b * CI * NPIX;
    unsigned* Ybu = d_yb + (size_t)b * 64 * NPIX;

    int tid  = threadIdx.x;
    int lane = tid & 31;
    int wid  = tid >> 5;
    int qb   = wid * 16;
    int r    = lane >> 2;
    int cq   = lane & 3;

    uint32_t kBase = smem_u32(sK);
    uint32_t gBase = smem_u32(sG);

    auto stageK = [&](int s, int m0k) {
        #pragma unroll
        for (int j = 0; j < 8; j++) {
            int idx = tid + j*128;
            int row = idx >> 4, seg = idx & 15;
            cp16(kBase + (uint32_t)((s*KS_STAGE + row*KS_STR + seg*4)*4),
                 Pt + (size_t)(m0k + row)*CI + seg*8);
        }
    };
    auto stageG = [&](int s, int m0k) {
        #pragma unroll
        for (int j = 0; j < 8; j++) {
            int idx = tid + j*128;
            int row = idx >> 3, seg = idx & 7;
            cp16(gBase + (uint32_t)((s*GS_STAGE + row*GS_STR + seg*4)*4),
                 Gp + (size_t)row*NPIX + m0k + seg*8);
        }
    };

    #pragma unroll
    for (int j = 0; j < 8; j++) {
        int idx = tid + j*128;
        int row = idx >> 4, seg = idx & 15;
        cp16(kBase + (uint32_t)((row*KS_STR + seg*4)*4),
             Tt + (size_t)(n0 + row)*CI + seg*8);
    }
    cp_commit();
    cp_wait<0>();
    __syncthreads();

    unsigned qa[8][4];
    #pragma unroll
    for (int ch = 0; ch < 8; ch++) {
        int ko = ch*8 + cq;
        qa[ch][0] = ldu(&sK[(qb + r)*KS_STR + ko]);
        qa[ch][1] = ldu(&sK[(qb + r + 8)*KS_STR + ko]);
        qa[ch][2] = ldu(&sK[(qb + r)*KS_STR + ko + 4]);
        qa[ch][3] = ldu(&sK[(qb + r + 8)*KS_STR + ko + 4]);
    }
    __syncthreads();

    stageK(0, 0); cp_commit();
    stageG(0, 0); cp_commit();

    float O[16][4];
    #pragma unroll
    for (int i = 0; i < 16; i++)
        #pragma unroll
        for (int j = 0; j < 4; j++) O[i][j] = 0.f;
    float Mx0 = -1e30f, Mx1 = -1e30f, L0 = 0.f, L1 = 0.f;
    const unsigned FULL = 0xffffffffu;

    for (int t = 0; t < 64; t++) {
        int s = t & 1;
        int m0 = t * 64;

        if (t < 63) { stageK(s^1, m0 + 64); cp_commit(); cp_wait<2>(); }
        else        cp_wait<1>();
        __syncthreads();

        const float* Kt = sK + s*KS_STAGE;
        float S[8][4];
        #pragma unroll
        for (int i = 0; i < 8; i++)
            #pragma unroll
            for (int j = 0; j < 4; j++) S[i][j] = 0.f;

        #pragma unroll
        for (int ch = 0; ch < 8; ch++) {
            int ko = ch*8 + cq;
            #pragma unroll
            for (int nt = 0; nt < 8; nt++) {
                unsigned b0 = ldu(&Kt[(nt*8 + r)*KS_STR + ko]);
                unsigned b1 = ldu(&Kt[(nt*8 + r)*KS_STR + ko + 4]);
                mma_bf16(S[nt], qa[ch][0], qa[ch][1], qa[ch][2], qa[ch][3], b0, b1);
            }
        }

        float rm0 = -1e30f, rm1 = -1e30f;
        #pragma unroll
        for (int nt = 0; nt < 8; nt++) {
            rm0 = fmaxf(rm0, fmaxf(S[nt][0], S[nt][1]));
            rm1 = fmaxf(rm1, fmaxf(S[nt][2], S[nt][3]));
        }
        rm0 = fmaxf(rm0, __shfl_xor_sync(FULL, rm0, 1));
        rm0 = fmaxf(rm0, __shfl_xor_sync(FULL, rm0, 2));
        rm1 = fmaxf(rm1, __shfl_xor_sync(FULL, rm1, 1));
        rm1 = fmaxf(rm1, __shfl_xor_sync(FULL, rm1, 2));

        float nm0 = fmaxf(Mx0, rm0), nm1 = fmaxf(Mx1, rm1);
        float sc0 = __expf(Mx0 - nm0), sc1 = __expf(Mx1 - nm1);
        Mx0 = nm0; Mx1 = nm1;

        float rs0 = 0.f, rs1 = 0.f;
        #pragma unroll
        for (int nt = 0; nt < 8; nt++) {
            S[nt][0] = __expf(S[nt][0] - nm0);
            S[nt][1] = __expf(S[nt][1] - nm0);
            S[nt][2] = __expf(S[nt][2] - nm1);
            S[nt][3] = __expf(S[nt][3] - nm1);
            rs0 += S[nt][0] + S[nt][1];
            rs1 += S[nt][2] + S[nt][3];
        }
        rs0 += __shfl_xor_sync(FULL, rs0, 1);
        rs0 += __shfl_xor_sync(FULL, rs0, 2);
        rs1 += __shfl_xor_sync(FULL, rs1, 1);
        rs1 += __shfl_xor_sync(FULL, rs1, 2);
        L0 = L0*sc0 + rs0;
        L1 = L1*sc1 + rs1;

        if (!__all_sync(FULL, (sc0 == 1.f) & (sc1 == 1.f))) {
            #pragma unroll
            for (int i = 0; i < 16; i++) {
                O[i][0] *= sc0; O[i][1] *= sc0;
                O[i][2] *= sc1; O[i][3] *= sc1;
            }
        }

        unsigned pa[4][4];
        #pragma unroll
        for (int kc = 0; kc < 4; kc++) {
            pa[kc][0] = pack_bf(S[2*kc][1],   S[2*kc][0]);
            pa[kc][1] = pack_bf(S[2*kc][3],   S[2*kc][2]);
            pa[kc][2] = pack_bf(S[2*kc+1][1], S[2*kc+1][0]);
            pa[kc][3] = pack_bf(S[2*kc+1][3], S[2*kc+1][2]);
        }

        if (t < 63) { stageG(s^1, m0 + 64); cp_commit(); cp_wait<2>(); }
        else        cp_wait<0>();
        __syncthreads();

        const float* Gt = sG + s*GS_STAGE;
        #pragma unroll
        for (int kc = 0; kc < 4; kc++) {
            int ko = kc*8 + cq;
            #pragma unroll
            for (int ct = 0; ct < 16; ct++) {
                unsigned b0 = ldu(&Gt[(ct*8 + r)*GS_STR + ko]);
                unsigned b1 = ldu(&Gt[(ct*8 + r)*GS_STR + ko + 4]);
                mma_bf16(O[ct], pa[kc][0], pa[kc][1], pa[kc][2], pa[kc][3], b0, b1);
            }
        }
    }

    float inv0 = 1.0f / L0, inv1 = 1.0f / L1;
    int q = n0 + qb + r;
    #pragma unroll
    for (int ct = 0; ct < 16; ct++) {
        int kp = ct*4 + cq;
        Ybu[(size_t)kp*NPIX + q]     = pack_bf(O[ct][1]*inv0, O[ct][0]*inv0);
        Ybu[(size_t)kp*NPIX + q + 8] = pack_bf(O[ct][3]*inv1, O[ct][2]*inv1);
    }
}

// ---------------- final: out = GN2(z)*0.1 + xs (totals read directly) -------------
__global__ void final_apply_kernel(const float* __restrict__ gw,
                                   const float* __restrict__ gb,
                                   float* __restrict__ out) {
    __shared__ float st[2];
    int bg = blockIdx.x >> 7;
    if (threadIdx.x == 0) {
        float S  = d_part2[bg*2];
        float S2 = d_part2[bg*2 + 1];
        float mean = S / (float)GSIZE;
        st[0] = mean;
        st[1] = rsqrtf(S2 / (float)GSIZE - mean*mean + EPSV);
    }
    __syncthreads();
    int i4 = blockIdx.x * blockDim.x + threadIdx.x;
    int idx = i4 << 2;
    int c   = (idx >> 12) & 255;
    float sc = st[1] * gw[c];
    float sh = gb[c] - st[0] * sc;
    float4 z = ((const float4*)d_z)[i4];
    float4 xs = ((const float4*)d_xs)[i4];
    float4 o;
    o.x = (z.x*sc + sh)*0.1f + xs.x;
    o.y = (z.y*sc + sh)*0.1f + xs.y;
    o.z = (z.z*sc + sh)*0.1f + xs.z;
    o.w = (z.w*sc + sh)*0.1f + xs.w;
    ((float4*)out)[i4] = o;
}

// ---------------- launch -----------------------------------------------------------
extern "C" void kernel_launch(void* const* d_in, const int* in_sizes, int n_in,
                              void* d_out, int out_size) {
    const float* x    = (const float*)d_in[0];
    const float* sw   = (const float*)d_in[1];
    const float* sb   = (const float*)d_in[2];
    const float* gn1w = (const float*)d_in[3];
    const float* gn1b = (const float*)d_in[4];
    const float* g_w  = (const float*)d_in[5];
    const float* g_b  = (const float*)d_in[6];
    const float* th_w = (const float*)d_in[7];
    const float* th_b = (const float*)d_in[8];
    const float* ph_w = (const float*)d_in[9];
    const float* ph_b = (const float*)d_in[10];
    const float* w_w  = (const float*)d_in[11];
    const float* w_b  = (const float*)d_in[12];
    const float* gn2w = (const float*)d_in[13];
    const float* gn2b = (const float*)d_in[14];
    float* out = (float*)d_out;

    static int attrSet = 0;
    if (!attrSet) {
        cudaFuncSetAttribute(conv_tc_kernel,
                             cudaFuncAttributeMaxDynamicSharedMemorySize, CONV_SMEM);
        cudaFuncSetAttribute(attention_tc_kernel,
                             cudaFuncAttributeMaxDynamicSharedMemorySize, ATTN_SMEM);
        attrSet = 1;
    }

    pack_w_bf_kernel<<<dim3(9, 256), 256>>>(sw);
    pack_qkvw_kernel<<<256, 256>>>(th_w, ph_w, g_w, w_w);   // also zeroes stats
    prep_x_kernel<<<dim3(128, 8, 4), dim3(32, 8)>>>(x);
    conv_tc_kernel<<<dim3(32, 4), 256, CONV_SMEM>>>(sb);
    gn1_apply_kernel<<<dim3(4, 128, 4), 256>>>(gn1w, gn1b);

    gemm_bf_kernel<0><<<dim3(32, 6, 4), 256>>>(th_b, ph_b, g_b);
    prep_attn_kernel<<<dim3(128, 4, 8), dim3(32, 8)>>>();

    attention_tc_kernel<<<dim3(64, 4), 128, ATTN_SMEM>>>();

    gemm_bf_kernel<3><<<dim3(32, 4, 4), 256>>>(w_b, nullptr, nullptr);
    final_apply_kernel<<<4096, 256>>>(gn2w, gn2b, out);

    (void)in_sizes; (void)n_in; (void)out_size;
}

// round 16
// speedup vs baseline: 1.1258x; 1.1030x over previous
#include <cuda_runtime.h>
#include <cuda_bf16.h>
#include <math.h>
#include <stdint.h>

#define BATCH 4
#define CCH   256
#define CI    128
#define NPIX  4096
#define GROUPS 8
#define CPG   32
#define GSIZE (CPG*NPIX)
#define EPSV  1e-5f
#define KCONV 2304

// ---------------- scratch ----------------------------------------------------
__device__ float d_xs   [BATCH*CCH*NPIX];
__device__ float d_xr   [BATCH*CCH*NPIX];      // x rounded to tf32 (fp32 storage)
__device__ float d_z    [BATCH*CCH*NPIX];
__device__ float d_wf   [CCH*KCONV];           // conv weights [m][tap*256+c], tf32-rna
__device__ unsigned d_xsb[BATCH*128*NPIX];
__device__ unsigned d_yb [BATCH*64*NPIX];
__device__ unsigned d_wpk[65536];
__device__ __nv_bfloat16 d_thb[BATCH*CI*NPIX];
__device__ __nv_bfloat16 d_phb[BATCH*CI*NPIX];
__device__ __nv_bfloat16 d_ttb[BATCH*NPIX*CI];
__device__ __nv_bfloat16 d_ptb[BATCH*NPIX*CI];
__device__ __nv_bfloat16 d_gb [BATCH*CI*NPIX];
__device__ float d_part1[64];
__device__ float d_part2[64];

// ---------------- helpers -----------------------------------------------------
__device__ __forceinline__ void mma_bf16(float* c,
    unsigned a0, unsigned a1, unsigned a2, unsigned a3,
    unsigned b0, unsigned b1) {
    asm volatile(
        "mma.sync.aligned.m16n8k16.row.col.f32.bf16.bf16.f32 "
        "{%0,%1,%2,%3}, {%4,%5,%6,%7}, {%8,%9}, {%0,%1,%2,%3};"
        : "+f"(c[0]), "+f"(c[1]), "+f"(c[2]), "+f"(c[3])
        : "r"(a0), "r"(a1), "r"(a2), "r"(a3), "r"(b0), "r"(b1));
}
__device__ __forceinline__ void mma_tf32(float* c,
    unsigned a0, unsigned a1, unsigned a2, unsigned a3,
    unsigned b0, unsigned b1) {
    asm volatile(
        "mma.sync.aligned.m16n8k8.row.col.f32.tf32.tf32.f32 "
        "{%0,%1,%2,%3}, {%4,%5,%6,%7}, {%8,%9}, {%0,%1,%2,%3};"
        : "+f"(c[0]), "+f"(c[1]), "+f"(c[2]), "+f"(c[3])
        : "r"(a0), "r"(a1), "r"(a2), "r"(a3), "r"(b0), "r"(b1));
}
__device__ __forceinline__ unsigned f2tf(float f) {
    unsigned u;
    asm("cvt.rna.tf32.f32 %0, %1;" : "=r"(u) : "f"(f));
    return u;
}
__device__ __forceinline__ unsigned pack_bf(float hi, float lo) {
    unsigned u;
    asm("cvt.rn.bf16x2.f32 %0, %1, %2;" : "=r"(u) : "f"(hi), "f"(lo));
    return u;
}
__device__ __forceinline__ void cp16(uint32_t dst, const void* src) {
    asm volatile("cp.async.cg.shared.global [%0], [%1], 16;" :: "r"(dst), "l"(src));
}
__device__ __forceinline__ void cp4z(uint32_t dst, const void* src, int srcsz) {
    asm volatile("cp.async.ca.shared.global [%0], [%1], 4, %2;"
                 :: "r"(dst), "l"(src), "r"(srcsz));
}
__device__ __forceinline__ void cp_commit() {
    asm volatile("cp.async.commit_group;");
}
template<int N>
__device__ __forceinline__ void cp_wait() {
    asm volatile("cp.async.wait_group %0;" :: "n"(N));
}
__device__ __forceinline__ uint32_t smem_u32(const void* p) {
    return (uint32_t)__cvta_generic_to_shared(p);
}
__device__ __forceinline__ unsigned ldu(const float* p) {
    return __float_as_uint(*p);
}
__device__ __forceinline__ void wred2(float& s, float& s2) {
    #pragma unroll
    for (int off = 16; off > 0; off >>= 1) {
        s  += __shfl_xor_sync(0xffffffffu, s,  off);
        s2 += __shfl_xor_sync(0xffffffffu, s2, off);
    }
}

// ---------------- precompute: conv weights -> [m][tap*256+c], tf32-rna ---------
__global__ void pack_wf_kernel(const float* __restrict__ w) {
    int k = blockIdx.x * 256 + threadIdx.x;   // grid (9, 256)
    int m = blockIdx.y;
    int c = k & 255, tap = k >> 8;
    d_wf[(size_t)m*KCONV + k] =
        __uint_as_float(f2tf(w[m*(CCH*9) + c*9 + tap]));
}

// ---------------- precompute: round x to tf32 (layout unchanged) ----------------
__global__ void round_x_kernel(const float* __restrict__ x) {
    int i4 = blockIdx.x * blockDim.x + threadIdx.x;   // over 1048576 float4s
    float4 v = ((const float4*)x)[i4];
    v.x = __uint_as_float(f2tf(v.x));
    v.y = __uint_as_float(f2tf(v.y));
    v.z = __uint_as_float(f2tf(v.z));
    v.w = __uint_as_float(f2tf(v.w));
    ((float4*)d_xr)[i4] = v;
}

// ---------------- precompute: pack qkv+w weights + zero stats -------------------
__global__ void pack_qkvw_kernel(const float* __restrict__ thw,
                                 const float* __restrict__ phw,
                                 const float* __restrict__ gw_,
                                 const float* __restrict__ ww) {
    int idx = blockIdx.x * 256 + threadIdx.x;
    if (idx < 64)  d_part1[idx] = 0.f;
    else if (idx < 128) d_part2[idx - 64] = 0.f;
    const float* src;
    int off, loc, K;
    if (idx < 16384)      { src = thw; off = 0;     loc = idx;         K = 256; }
    else if (idx < 32768) { src = phw; off = 16384; loc = idx - 16384; K = 256; }
    else if (idx < 49152) { src = gw_; off = 32768; loc = idx - 32768; K = 256; }
    else                  { src = ww;  off = 49152; loc = idx - 49152; K = 128; }
    int kp = loc & (K/2 - 1);
    int m  = loc / (K/2);
    d_wpk[off + loc] = pack_bf(src[m*K + kp*2 + 1], src[m*K + kp*2]);
}

// ---------------- prep attention: transpose theta/phi bf16 -> [n][c] -----------
__global__ void prep_attn_kernel() {
    __shared__ __nv_bfloat16 t[32][34];
    int which = blockIdx.z & 1, b = blockIdx.z >> 1;
    const __nv_bfloat16* src = (which ? d_phb : d_thb) + (size_t)b*CI*NPIX;
    __nv_bfloat16* dst = (which ? d_ptb : d_ttb) + (size_t)b*NPIX*CI;
    int n0 = blockIdx.x * 32, c0 = blockIdx.y * 32;
    int tx = threadIdx.x, ty = threadIdx.y;
    #pragma unroll
    for (int i = 0; i < 4; i++)
        t[ty + i*8][tx] = src[(size_t)(c0 + ty + i*8)*NPIX + n0 + tx];
    __syncthreads();
    #pragma unroll
    for (int i = 0; i < 4; i++) {
        int n = ty + i*8;
        dst[(size_t)(n0 + n)*CI + c0 + tx] = t[tx][n];
    }
}

// ---------------- conv3x3 implicit GEMM: single-pass tf32 m16n8k8 ---------------
// 256m x 128pix block, 8 warps (4m x 2n), warp 64x64. K-chunk 64.
#define CVA_STR 68
#define CVB_STR 132
#define CVA_PLANE (256*CVA_STR)              // 17408 floats
#define CVB_PLANE (64*CVB_STR)               // 8448 floats
#define CV_STAGE (CVA_PLANE + CVB_PLANE)     // 25856 floats
#define CONV_SMEM (2*CV_STAGE*4)             // 206848 bytes

__global__ void __launch_bounds__(256, 1) conv_tc_kernel(const float* __restrict__ sb) {
    extern __shared__ float smem[];

    int b    = blockIdx.y;
    int pix0 = blockIdx.x * 128;
    int h0   = pix0 >> 6;

    int tid  = threadIdx.x;
    int lane = tid & 31;
    int wid  = tid >> 5;
    int wm = wid >> 1, wn = wid & 1;
    int r  = lane >> 2, cq = lane & 3;

    uint32_t base = smem_u32(smem);

    float C[32][4];
    #pragma unroll
    for (int i = 0; i < 32; i++)
        #pragma unroll
        for (int j = 0; j < 4; j++) C[i][j] = 0.f;

    auto stage = [&](int st, int kc) {
        int tap = kc >> 8;
        int c0  = kc & 255;
        int ky  = tap/3 - 1;
        int kx  = tap - (tap/3)*3 - 1;
        uint32_t sb0 = base + (uint32_t)(st*CV_STAGE*4);
        // A: 256 rows x 16 segs(16B) = 4096 cp16 -> 16/thread
        #pragma unroll
        for (int j = 0; j < 16; j++) {
            int idx = tid + j*256;
            int row = idx >> 4;
            int seg = idx & 15;
            cp16(sb0 + (uint32_t)((row*CVA_STR + seg*4)*4),
                 d_wf + (size_t)row*KCONV + kc + seg*4);
        }
        // B: 64 rows (k=c) x 128 px = 8192 cp4 -> 32/thread (im2col, per-px valid)
        #pragma unroll
        for (int j = 0; j < 32; j++) {
            int idx = tid + j*256;
            int row = idx >> 7;
            int n   = idx & 127;
            int h = h0 + (n >> 6) + ky;
            int w = (n & 63) + kx;
            int valid = ((unsigned)h < 64u) & ((unsigned)w < 64u);
            int pix = valid ? (h*64 + w) : 0;
            cp4z(sb0 + (uint32_t)((CVA_PLANE + row*CVB_STR + n)*4),
                 d_xr + ((size_t)(b*CCH + c0 + row))*NPIX + pix,
                 valid ? 4 : 0);
        }
    };

    stage(0, 0);
    cp_commit();

    for (int it = 0; it < 36; it++) {
        if (it < 35) { stage((it+1) & 1, (it+1)*64); cp_commit(); cp_wait<1>(); }
        else cp_wait<0>();
        __syncthreads();

        const float* A = smem + (it & 1)*CV_STAGE;
        const float* B = A + CVA_PLANE;

        #pragma unroll
        for (int ch = 0; ch < 8; ch++) {
            int ko = ch*8 + cq;
            unsigned a[4][4];
            #pragma unroll
            for (int mt = 0; mt < 4; mt++) {
                int m = wm*64 + mt*16 + r;
                a[mt][0] = ldu(&A[m*CVA_STR + ko]);
                a[mt][1] = ldu(&A[(m+8)*CVA_STR + ko]);
                a[mt][2] = ldu(&A[m*CVA_STR + ko + 4]);
                a[mt][3] = ldu(&A[(m+8)*CVA_STR + ko + 4]);
            }
            unsigned bf[8][2];
            #pragma unroll
            for (int nt = 0; nt < 8; nt++) {
                int n = wn*64 + nt*8 + r;
                bf[nt][0] = ldu(&B[ko*CVB_STR + n]);
                bf[nt][1] = ldu(&B[(ko+4)*CVB_STR + n]);
            }
            #pragma unroll
            for (int mt = 0; mt < 4; mt++)
                #pragma unroll
                for (int nt = 0; nt < 8; nt++)
                    mma_tf32(C[mt*8+nt], a[mt][0], a[mt][1], a[mt][2], a[mt][3],
                             bf[nt][0], bf[nt][1]);
        }
        __syncthreads();
    }

    // epilogue: store + fused GN1 partial stats
    #pragma unroll
    for (int mt = 0; mt < 4; mt++) {
        int m = wm*64 + mt*16 + r;
        float bv0 = sb[m], bv8 = sb[m + 8];
        float s = 0.f, s2 = 0.f;
        #pragma unroll
        for (int nt = 0; nt < 8; nt++) {
            int n = pix0 + wn*64 + nt*8 + 2*cq;
            float* cf = C[mt*8 + nt];
            float v0 = cf[0]+bv0, v1 = cf[1]+bv0, v2 = cf[2]+bv8, v3 = cf[3]+bv8;
            *(float2*)&d_xs[((size_t)(b*CCH + m))*NPIX + n]     = make_float2(v0, v1);
            *(float2*)&d_xs[((size_t)(b*CCH + m + 8))*NPIX + n] = make_float2(v2, v3);
            s  += v0 + v1 + v2 + v3;
            s2 += v0*v0 + v1*v1 + v2*v2 + v3*v3;
        }
        wred2(s, s2);
        if (lane == 0) {
            int bg = b*8 + wm*2 + (mt >> 1);
            atomicAdd(&d_part1[bg*2],     s);
            atomicAdd(&d_part1[bg*2 + 1], s2);
        }
    }
}

// ---------------- GN1 apply + ReLU ----------------------------------------------
__global__ void gn1_apply_kernel(const float* __restrict__ gw,
                                 const float* __restrict__ gb) {
    __shared__ float st[2];
    int b  = blockIdx.z;
    int kp = blockIdx.y;
    int c  = kp << 1;
    int bg = b*8 + (kp >> 4);
    if (threadIdx.x == 0) {
        float S  = d_part1[bg*2];
        float S2 = d_part1[bg*2 + 1];
        float mean = S / (float)GSIZE;
        st[0] = mean;
        st[1] = rsqrtf(S2 / (float)GSIZE - mean*mean + EPSV);
    }
    __syncthreads();
    float sc0 = st[1] * gw[c],   sh0 = gb[c]   - st[0]*sc0;
    float sc1 = st[1] * gw[c+1], sh1 = gb[c+1] - st[0]*sc1;
    int n = blockIdx.x*1024 + threadIdx.x*4;
    size_t base = ((size_t)(b*CCH + c))*NPIX + n;
    float4 v0 = *(float4*)&d_xs[base];
    float4 v1 = *(float4*)&d_xs[base + NPIX];
    v0.x = fmaxf(v0.x*sc0 + sh0, 0.f); v0.y = fmaxf(v0.y*sc0 + sh0, 0.f);
    v0.z = fmaxf(v0.z*sc0 + sh0, 0.f); v0.w = fmaxf(v0.w*sc0 + sh0, 0.f);
    v1.x = fmaxf(v1.x*sc1 + sh1, 0.f); v1.y = fmaxf(v1.y*sc1 + sh1, 0.f);
    v1.z = fmaxf(v1.z*sc1 + sh1, 0.f); v1.w = fmaxf(v1.w*sc1 + sh1, 0.f);
    *(float4*)&d_xs[base]        = v0;
    *(float4*)&d_xs[base + NPIX] = v1;
    uint4 pk;
    pk.x = pack_bf(v1.x, v0.x);
    pk.y = pack_bf(v1.y, v0.y);
    pk.z = pack_bf(v1.z, v0.z);
    pk.w = pack_bf(v1.w, v0.w);
    *(uint4*)&d_xsb[((size_t)(b*128 + kp))*NPIX + n] = pk;
}

// ---------------- bf16 1x1 GEMM (R15) ---------------------------------------------
template<int MODE>
__global__ void __launch_bounds__(256) gemm_bf_kernel(const float* __restrict__ bias0,
                                                      const float* __restrict__ bias1,
                                                      const float* __restrict__ bias2) {
    constexpr int K  = (MODE == 3) ? 128 : 256;
    constexpr int KP = K / 2;
    constexpr int NI = K / 32;
    const unsigned* Wp = d_wpk + (MODE == 3 ? 49152 : 0);
    const unsigned* Xall = (MODE == 3) ? d_yb : d_xsb;

    __shared__ unsigned Ws[2][64*20];
    __shared__ unsigned Xs[2][16*132];

    int b  = blockIdx.z;
    int n0 = blockIdx.x * 128;
    int m0 = blockIdx.y * 64;
    const unsigned* Xb = Xall + (size_t)b * KP * NPIX;

    int tid  = threadIdx.x;
    int lane = tid & 31;
    int wid  = tid >> 5;
    int wm = wid >> 2, wn = wid & 3;
    int r  = lane >> 2, cq = lane & 3;

    int wRow = tid >> 2, wSeg = tid & 3;
    int xRow = tid >> 5, xSeg = tid & 31;
    uint32_t wBase = smem_u32(Ws);
    uint32_t xBase = smem_u32(Xs);

    auto stage = [&](int s, int it) {
        int kp0 = it * 16;
        cp16(wBase + (uint32_t)((s*64*20 + wRow*20 + wSeg*4)*4),
             Wp + (size_t)(m0 + wRow)*KP + kp0 + wSeg*4);
        #pragma unroll
        for (int j = 0; j < 2; j++) {
            int k = xRow + j*8;
            cp16(xBase + (uint32_t)((s*16*132 + k*132 + xSeg*4)*4),
                 Xb + (size_t)(kp0 + k)*NPIX + n0 + xSeg*4);
        }
    };

    float C[8][4];
    #pragma unroll
    for (int i = 0; i < 8; i++)
        #pragma unroll
        for (int j = 0; j < 4; j++) C[i][j] = 0.f;

    stage(0, 0);
    cp_commit();

    for (int it = 0; it < NI; it++) {
        if (it < NI-1) { stage((it+1)&1, it+1); cp_commit(); cp_wait<1>(); }
        else cp_wait<0>();
        __syncthreads();

        const unsigned* Wt = Ws[it & 1];
        const unsigned* Xt = Xs[it & 1];

        #pragma unroll
        for (int ch = 0; ch < 2; ch++) {
            int ko = ch*8 + cq;
            unsigned a[2][4];
            #pragma unroll
            for (int mt = 0; mt < 2; mt++) {
                int mr = wm*32 + mt*16 + r;
                a[mt][0] = Wt[mr*20 + ko];
                a[mt][1] = Wt[(mr+8)*20 + ko];
                a[mt][2] = Wt[mr*20 + ko + 4];
                a[mt][3] = Wt[(mr+8)*20 + ko + 4];
            }
            #pragma unroll
            for (int nt = 0; nt < 4; nt++) {
                int nn = wn*32 + nt*8 + r;
                unsigned b0 = Xt[ko*132 + nn];
                unsigned b1 = Xt[(ko+4)*132 + nn];
                mma_bf16(C[nt],     a[0][0], a[0][1], a[0][2], a[0][3], b0, b1);
                mma_bf16(C[4 + nt], a[1][0], a[1][1], a[1][2], a[1][3], b0, b1);
            }
        }
        __syncthreads();
    }

    const float* bias = (MODE == 3) ? bias0
                      : (m0 < 128 ? bias0 : m0 < 256 ? bias1 : bias2);
    int mbase = (MODE == 3) ? m0 : (m0 & 127);
    __nv_bfloat16* Obf = nullptr;
    if (MODE != 3)
        Obf = (m0 < 128 ? d_thb : m0 < 256 ? d_phb : d_gb) + (size_t)b * CI * NPIX;

    float s = 0.f, s2 = 0.f;
    #pragma unroll
    for (int mt = 0; mt < 2; mt++) {
        int ml = mbase + wm*32 + mt*16 + r;
        float bv0 = bias[ml], bv8 = bias[ml + 8];
        #pragma unroll
        for (int nt = 0; nt < 4; nt++) {
            int n = n0 + wn*32 + nt*8 + 2*cq;
            float* cf = C[mt*4 + nt];
            if (MODE == 3) {
                float v0 = cf[0]+bv0, v1 = cf[1]+bv0, v2 = cf[2]+bv8, v3 = cf[3]+bv8;
                float* Ob = d_z + (size_t)b * CCH * NPIX;
                *(float2*)&Ob[(size_t)ml*NPIX + n]     = make_float2(v0, v1);
                *(float2*)&Ob[(size_t)(ml+8)*NPIX + n] = make_float2(v2, v3);
                s  += v0 + v1 + v2 + v3;
                s2 += v0*v0 + v1*v1 + v2*v2 + v3*v3;
            } else {
                *(unsigned*)&Obf[(size_t)ml*NPIX + n]     = pack_bf(cf[1]+bv0, cf[0]+bv0);
                *(unsigned*)&Obf[(size_t)(ml+8)*NPIX + n] = pack_bf(cf[3]+bv8, cf[2]+bv8);
            }
        }
    }
    if (MODE == 3) {
        wred2(s, s2);
        if (lane == 0) {
            int bg = b*8 + (m0 >> 5) + wm;
            atomicAdd(&d_part2[bg*2],     s);
            atomicAdd(&d_part2[bg*2 + 1], s2);
        }
    }
}

// ---------------- bf16 flash attention (R15) --------------------------------------
#define KS_STR 68
#define KS_STAGE (64*KS_STR)
#define GS_STR 36
#define GS_STAGE (128*GS_STR)
#define ATTN_SMEM ((2*KS_STAGE + 2*GS_STAGE)*4)

__global__ void __launch_bounds__(128, 2) attention_tc_kernel() {
    extern __shared__ float smem[];
    float* sK = smem;
    float* sG = smem + 2*KS_STAGE;

    int b  = blockIdx.y;
    int n0 = blockIdx.x * 64;
    const __nv_bfloat16* Tt = d_ttb + (size_t)b * NPIX * CI;
    const __nv_bfloat16* Pt = d_ptb + (size_t)b * NPIX * CI;
    const __nv_bfloat16* Gp = d_gb  + (size_t)b * CI * NPIX;
    unsigned* Ybu = d_yb + (size_t)b * 64 * NPIX;

    int tid  = threadIdx.x;
    int lane = tid & 31;
    int wid  = tid >> 5;
    int qb   = wid * 16;
    int r    = lane >> 2;
    int cq   = lane & 3;

    uint32_t kBase = smem_u32(sK);
    uint32_t gBase = smem_u32(sG);

    auto stageK = [&](int s, int m0k) {
        #pragma unroll
        for (int j = 0; j < 8; j++) {
            int idx = tid + j*128;
            int row = idx >> 4, seg = idx & 15;
            cp16(kBase + (uint32_t)((s*KS_STAGE + row*KS_STR + seg*4)*4),
                 Pt + (size_t)(m0k + row)*CI + seg*8);
        }
    };
    auto stageG = [&](int s, int m0k) {
        #pragma unroll
        for (int j = 0; j < 8; j++) {
            int idx = tid + j*128;
            int row = idx >> 3, seg = idx & 7;
            cp16(gBase + (uint32_t)((s*GS_STAGE + row*GS_STR + seg*4)*4),
                 Gp + (size_t)row*NPIX + m0k + seg*8);
        }
    };

    #pragma unroll
    for (int j = 0; j < 8; j++) {
        int idx = tid + j*128;
        int row = idx >> 4, seg = idx & 15;
        cp16(kBase + (uint32_t)((row*KS_STR + seg*4)*4),
             Tt + (size_t)(n0 + row)*CI + seg*8);
    }
    cp_commit();
    cp_wait<0>();
    __syncthreads();

    unsigned qa[8][4];
    #pragma unroll
    for (int ch = 0; ch < 8; ch++) {
        int ko = ch*8 + cq;
        qa[ch][0] = ldu(&sK[(qb + r)*KS_STR + ko]);
        qa[ch][1] = ldu(&sK[(qb + r + 8)*KS_STR + ko]);
        qa[ch][2] = ldu(&sK[(qb + r)*KS_STR + ko + 4]);
        qa[ch][3] = ldu(&sK[(qb + r + 8)*KS_STR + ko + 4]);
    }
    __syncthreads();

    stageK(0, 0); cp_commit();
    stageG(0, 0); cp_commit();

    float O[16][4];
    #pragma unroll
    for (int i = 0; i < 16; i++)
        #pragma unroll
        for (int j = 0; j < 4; j++) O[i][j] = 0.f;
    float Mx0 = -1e30f, Mx1 = -1e30f, L0 = 0.f, L1 = 0.f;
    const unsigned FULL = 0xffffffffu;

    for (int t = 0; t < 64; t++) {
        int s = t & 1;
        int m0 = t * 64;

        if (t < 63) { stageK(s^1, m0 + 64); cp_commit(); cp_wait<2>(); }
        else        cp_wait<1>();
        __syncthreads();

        const float* Kt = sK + s*KS_STAGE;
        float S[8][4];
        #pragma unroll
        for (int i = 0; i < 8; i++)
            #pragma unroll
            for (int j = 0; j < 4; j++) S[i][j] = 0.f;

        #pragma unroll
        for (int ch = 0; ch < 8; ch++) {
            int ko = ch*8 + cq;
            #pragma unroll
            for (int nt = 0; nt < 8; nt++) {
                unsigned b0 = ldu(&Kt[(nt*8 + r)*KS_STR + ko]);
                unsigned b1 = ldu(&Kt[(nt*8 + r)*KS_STR + ko + 4]);
                mma_bf16(S[nt], qa[ch][0], qa[ch][1], qa[ch][2], qa[ch][3], b0, b1);
            }
        }

        float rm0 = -1e30f, rm1 = -1e30f;
        #pragma unroll
        for (int nt = 0; nt < 8; nt++) {
            rm0 = fmaxf(rm0, fmaxf(S[nt][0], S[nt][1]));
            rm1 = fmaxf(rm1, fmaxf(S[nt][2], S[nt][3]));
        }
        rm0 = fmaxf(rm0, __shfl_xor_sync(FULL, rm0, 1));
        rm0 = fmaxf(rm0, __shfl_xor_sync(FULL, rm0, 2));
        rm1 = fmaxf(rm1, __shfl_xor_sync(FULL, rm1, 1));
        rm1 = fmaxf(rm1, __shfl_xor_sync(FULL, rm1, 2));

        float nm0 = fmaxf(Mx0, rm0), nm1 = fmaxf(Mx1, rm1);
        float sc0 = __expf(Mx0 - nm0), sc1 = __expf(Mx1 - nm1);
        Mx0 = nm0; Mx1 = nm1;

        float rs0 = 0.f, rs1 = 0.f;
        #pragma unroll
        for (int nt = 0; nt < 8; nt++) {
            S[nt][0] = __expf(S[nt][0] - nm0);
            S[nt][1] = __expf(S[nt][1] - nm0);
            S[nt][2] = __expf(S[nt][2] - nm1);
            S[nt][3] = __expf(S[nt][3] - nm1);
            rs0 += S[nt][0] + S[nt][1];
            rs1 += S[nt][2] + S[nt][3];
        }
        rs0 += __shfl_xor_sync(FULL, rs0, 1);
        rs0 += __shfl_xor_sync(FULL, rs0, 2);
        rs1 += __shfl_xor_sync(FULL, rs1, 1);
        rs1 += __shfl_xor_sync(FULL, rs1, 2);
        L0 = L0*sc0 + rs0;
        L1 = L1*sc1 + rs1;

        if (!__all_sync(FULL, (sc0 == 1.f) & (sc1 == 1.f))) {
            #pragma unroll
            for (int i = 0; i < 16; i++) {
                O[i][0] *= sc0; O[i][1] *= sc0;
                O[i][2] *= sc1; O[i][3] *= sc1;
            }
        }

        unsigned pa[4][4];
        #pragma unroll
        for (int kc = 0; kc < 4; kc++) {
            pa[kc][0] = pack_bf(S[2*kc][1],   S[2*kc][0]);
            pa[kc][1] = pack_bf(S[2*kc][3],   S[2*kc][2]);
            pa[kc][2] = pack_bf(S[2*kc+1][1], S[2*kc+1][0]);
            pa[kc][3] = pack_bf(S[2*kc+1][3], S[2*kc+1][2]);
        }

        if (t < 63) { stageG(s^1, m0 + 64); cp_commit(); cp_wait<2>(); }
        else        cp_wait<0>();
        __syncthreads();

        const float* Gt = sG + s*GS_STAGE;
        #pragma unroll
        for (int kc = 0; kc < 4; kc++) {
            int ko = kc*8 + cq;
            #pragma unroll
            for (int ct = 0; ct < 16; ct++) {
                unsigned b0 = ldu(&Gt[(ct*8 + r)*GS_STR + ko]);
                unsigned b1 = ldu(&Gt[(ct*8 + r)*GS_STR + ko + 4]);
                mma_bf16(O[ct], pa[kc][0], pa[kc][1], pa[kc][2], pa[kc][3], b0, b1);
            }
        }
    }

    float inv0 = 1.0f / L0, inv1 = 1.0f / L1;
    int q = n0 + qb + r;
    #pragma unroll
    for (int ct = 0; ct < 16; ct++) {
        int kp = ct*4 + cq;
        Ybu[(size_t)kp*NPIX + q]     = pack_bf(O[ct][1]*inv0, O[ct][0]*inv0);
        Ybu[(size_t)kp*NPIX + q + 8] = pack_bf(O[ct][3]*inv1, O[ct][2]*inv1);
    }
}

// ---------------- final: out = GN2(z)*0.1 + xs ------------------------------------
__global__ void final_apply_kernel(const float* __restrict__ gw,
                                   const float* __restrict__ gb,
                                   float* __restrict__ out) {
    __shared__ float st[2];
    int bg = blockIdx.x >> 7;
    if (threadIdx.x == 0) {
        float S  = d_part2[bg*2];
        float S2 = d_part2[bg*2 + 1];
        float mean = S / (float)GSIZE;
        st[0] = mean;
        st[1] = rsqrtf(S2 / (float)GSIZE - mean*mean + EPSV);
    }
    __syncthreads();
    int i4 = blockIdx.x * blockDim.x + threadIdx.x;
    int idx = i4 << 2;
    int c   = (idx >> 12) & 255;
    float sc = st[1] * gw[c];
    float sh = gb[c] - st[0] * sc;
    float4 z = ((const float4*)d_z)[i4];
    float4 xs = ((const float4*)d_xs)[i4];
    float4 o;
    o.x = (z.x*sc + sh)*0.1f + xs.x;
    o.y = (z.y*sc + sh)*0.1f + xs.y;
    o.z = (z.z*sc + sh)*0.1f + xs.z;
    o.w = (z.w*sc + sh)*0.1f + xs.w;
    ((float4*)out)[i4] = o;
}

// ---------------- launch -----------------------------------------------------------
extern "C" void kernel_launch(void* const* d_in, const int* in_sizes, int n_in,
                              void* d_out, int out_size) {
    const float* x    = (const float*)d_in[0];
    const float* sw   = (const float*)d_in[1];
    const float* sb   = (const float*)d_in[2];
    const float* gn1w = (const float*)d_in[3];
    const float* gn1b = (const float*)d_in[4];
    const float* g_w  = (const float*)d_in[5];
    const float* g_b  = (const float*)d_in[6];
    const float* th_w = (const float*)d_in[7];
    const float* th_b = (const float*)d_in[8];
    const float* ph_w = (const float*)d_in[9];
    const float* ph_b = (const float*)d_in[10];
    const float* w_w  = (const float*)d_in[11];
    const float* w_b  = (const float*)d_in[12];
    const float* gn2w = (const float*)d_in[13];
    const float* gn2b = (const float*)d_in[14];
    float* out = (float*)d_out;

    static int attrSet = 0;
    if (!attrSet) {
        cudaFuncSetAttribute(conv_tc_kernel,
                             cudaFuncAttributeMaxDynamicSharedMemorySize, CONV_SMEM);
        cudaFuncSetAttribute(attention_tc_kernel,
                             cudaFuncAttributeMaxDynamicSharedMemorySize, ATTN_SMEM);
        attrSet = 1;
    }

    pack_wf_kernel<<<dim3(9, 256), 256>>>(sw);
    pack_qkvw_kernel<<<256, 256>>>(th_w, ph_w, g_w, w_w);   // also zeroes stats
    round_x_kernel<<<4096, 256>>>(x);
    conv_tc_kernel<<<dim3(32, 4), 256, CONV_SMEM>>>(sb);
    gn1_apply_kernel<<<dim3(4, 128, 4), 256>>>(gn1w, gn1b);

    gemm_bf_kernel<0><<<dim3(32, 6, 4), 256>>>(th_b, ph_b, g_b);
    prep_attn_kernel<<<dim3(128, 4, 8), dim3(32, 8)>>>();

    attention_tc_kernel<<<dim3(64, 4), 128, ATTN_SMEM>>>();

    gemm_bf_kernel<3><<<dim3(32, 4, 4), 256>>>(w_b, nullptr, nullptr);
    final_apply_kernel<<<4096, 256>>>(gn2w, gn2b, out);

    (void)in_sizes; (void)n_in; (void)out_size;
}

// round 17
// speedup vs baseline: 1.1727x; 1.0417x over previous
#include <cuda_runtime.h>
#include <cuda_bf16.h>
#include <math.h>
#include <stdint.h>

#define BATCH 4
#define CCH   256
#define CI    128
#define NPIX  4096
#define GROUPS 8
#define CPG   32
#define GSIZE (CPG*NPIX)
#define EPSV  1e-5f
#define KCONV 2304

// ---------------- scratch ----------------------------------------------------
__device__ float d_xs   [BATCH*CCH*NPIX];
__device__ float d_xr   [BATCH*CCH*NPIX];      // x rounded to tf32
__device__ float d_z    [BATCH*CCH*NPIX];
__device__ float d_wf   [CCH*KCONV];           // conv weights [m][tap*256+c], tf32-rna
__device__ unsigned d_xsb[BATCH*128*NPIX];
__device__ unsigned d_yb [BATCH*64*NPIX];
__device__ unsigned d_wpk[65536];
__device__ __nv_bfloat16 d_thb[BATCH*CI*NPIX];
__device__ __nv_bfloat16 d_phb[BATCH*CI*NPIX];
__device__ __nv_bfloat16 d_ttb[BATCH*NPIX*CI];
__device__ __nv_bfloat16 d_ptb[BATCH*NPIX*CI];
__device__ __nv_bfloat16 d_gb [BATCH*CI*NPIX];
__device__ float d_part1[64];
__device__ float d_part2[64];

// ---------------- helpers -----------------------------------------------------
__device__ __forceinline__ void mma_bf16(float* c,
    unsigned a0, unsigned a1, unsigned a2, unsigned a3,
    unsigned b0, unsigned b1) {
    asm volatile(
        "mma.sync.aligned.m16n8k16.row.col.f32.bf16.bf16.f32 "
        "{%0,%1,%2,%3}, {%4,%5,%6,%7}, {%8,%9}, {%0,%1,%2,%3};"
        : "+f"(c[0]), "+f"(c[1]), "+f"(c[2]), "+f"(c[3])
        : "r"(a0), "r"(a1), "r"(a2), "r"(a3), "r"(b0), "r"(b1));
}
__device__ __forceinline__ void mma_tf32(float* c,
    unsigned a0, unsigned a1, unsigned a2, unsigned a3,
    unsigned b0, unsigned b1) {
    asm volatile(
        "mma.sync.aligned.m16n8k8.row.col.f32.tf32.tf32.f32 "
        "{%0,%1,%2,%3}, {%4,%5,%6,%7}, {%8,%9}, {%0,%1,%2,%3};"
        : "+f"(c[0]), "+f"(c[1]), "+f"(c[2]), "+f"(c[3])
        : "r"(a0), "r"(a1), "r"(a2), "r"(a3), "r"(b0), "r"(b1));
}
__device__ __forceinline__ unsigned f2tf(float f) {
    unsigned u;
    asm("cvt.rna.tf32.f32 %0, %1;" : "=r"(u) : "f"(f));
    return u;
}
__device__ __forceinline__ unsigned pack_bf(float hi, float lo) {
    unsigned u;
    asm("cvt.rn.bf16x2.f32 %0, %1, %2;" : "=r"(u) : "f"(hi), "f"(lo));
    return u;
}
__device__ __forceinline__ void cp16(uint32_t dst, const void* src) {
    asm volatile("cp.async.cg.shared.global [%0], [%1], 16;" :: "r"(dst), "l"(src));
}
__device__ __forceinline__ void cp16z(uint32_t dst, const void* src, int srcsz) {
    asm volatile("cp.async.cg.shared.global [%0], [%1], 16, %2;"
                 :: "r"(dst), "l"(src), "r"(srcsz));
}
__device__ __forceinline__ void cp_commit() {
    asm volatile("cp.async.commit_group;");
}
template<int N>
__device__ __forceinline__ void cp_wait() {
    asm volatile("cp.async.wait_group %0;" :: "n"(N));
}
__device__ __forceinline__ uint32_t smem_u32(const void* p) {
    return (uint32_t)__cvta_generic_to_shared(p);
}
__device__ __forceinline__ unsigned ldu(const float* p) {
    return __float_as_uint(*p);
}
__device__ __forceinline__ void wred2(float& s, float& s2) {
    #pragma unroll
    for (int off = 16; off > 0; off >>= 1) {
        s  += __shfl_xor_sync(0xffffffffu, s,  off);
        s2 += __shfl_xor_sync(0xffffffffu, s2, off);
    }
}

// ---------------- precompute: conv weights -> [m][tap*256+c], tf32-rna ---------
__global__ void pack_wf_kernel(const float* __restrict__ w) {
    int k = blockIdx.x * 256 + threadIdx.x;
    int m = blockIdx.y;
    int c = k & 255, tap = k >> 8;
    d_wf[(size_t)m*KCONV + k] =
        __uint_as_float(f2tf(w[m*(CCH*9) + c*9 + tap]));
}

// ---------------- precompute: round x to tf32 ----------------------------------
__global__ void round_x_kernel(const float* __restrict__ x) {
    int i4 = blockIdx.x * blockDim.x + threadIdx.x;
    float4 v = ((const float4*)x)[i4];
    v.x = __uint_as_float(f2tf(v.x));
    v.y = __uint_as_float(f2tf(v.y));
    v.z = __uint_as_float(f2tf(v.z));
    v.w = __uint_as_float(f2tf(v.w));
    ((float4*)d_xr)[i4] = v;
}

// ---------------- precompute: pack qkv+w weights + zero stats -------------------
__global__ void pack_qkvw_kernel(const float* __restrict__ thw,
                                 const float* __restrict__ phw,
                                 const float* __restrict__ gw_,
                                 const float* __restrict__ ww) {
    int idx = blockIdx.x * 256 + threadIdx.x;
    if (idx < 64)  d_part1[idx] = 0.f;
    else if (idx < 128) d_part2[idx - 64] = 0.f;
    const float* src;
    int off, loc, K;
    if (idx < 16384)      { src = thw; off = 0;     loc = idx;         K = 256; }
    else if (idx < 32768) { src = phw; off = 16384; loc = idx - 16384; K = 256; }
    else if (idx < 49152) { src = gw_; off = 32768; loc = idx - 32768; K = 256; }
    else                  { src = ww;  off = 49152; loc = idx - 49152; K = 128; }
    int kp = loc & (K/2 - 1);
    int m  = loc / (K/2);
    d_wpk[off + loc] = pack_bf(src[m*K + kp*2 + 1], src[m*K + kp*2]);
}

// ---------------- prep attention: transpose theta/phi bf16 -> [n][c] -----------
__global__ void prep_attn_kernel() {
    __shared__ __nv_bfloat16 t[32][34];
    int which = blockIdx.z & 1, b = blockIdx.z >> 1;
    const __nv_bfloat16* src = (which ? d_phb : d_thb) + (size_t)b*CI*NPIX;
    __nv_bfloat16* dst = (which ? d_ptb : d_ttb) + (size_t)b*NPIX*CI;
    int n0 = blockIdx.x * 32, c0 = blockIdx.y * 32;
    int tx = threadIdx.x, ty = threadIdx.y;
    #pragma unroll
    for (int i = 0; i < 4; i++)
        t[ty + i*8][tx] = src[(size_t)(c0 + ty + i*8)*NPIX + n0 + tx];
    __syncthreads();
    #pragma unroll
    for (int i = 0; i < 4; i++) {
        int n = ty + i*8;
        dst[(size_t)(n0 + n)*CI + c0 + tx] = t[tx][n];
    }
}

// ---------------- conv3x3 tf32, x-tile resident across taps ---------------------
// Loop: cc (4 chunks of 64 ch) x tap (9). A double-buffered per (cc,tap);
// x-tile [64ch][4 rows][72f pad, core @ j=4] persistent per cc.
#define CVA_STR 68
#define CVA_PLANE (256*CVA_STR)          // 17408 floats
#define CX_CSTR 292
#define CX_RSTR 72
#define CX_PLANE (64*CX_CSTR)            // 18688 floats
#define CONV_SMEM ((2*CVA_PLANE + CX_PLANE)*4)   // 214016 B

__global__ void __launch_bounds__(256, 1) conv_tc_kernel(const float* __restrict__ sb) {
    extern __shared__ float smem[];
    float* sX = smem + 2*CVA_PLANE;

    int b    = blockIdx.y;
    int pix0 = blockIdx.x * 128;
    int h0   = pix0 >> 6;

    int tid  = threadIdx.x;
    int lane = tid & 31;
    int wid  = tid >> 5;
    int wm = wid >> 1, wn = wid & 1;
    int r  = lane >> 2, cq = lane & 3;

    uint32_t base  = smem_u32(smem);
    uint32_t xbase = smem_u32(sX);

    // zero x-tile borders (j=3 and j=68), written once, never overwritten
    #pragma unroll
    for (int j = 0; j < 2; j++) {
        int idx = tid + j*256;
        int c = idx >> 3, rem = idx & 7;
        int row = rem >> 1, side = rem & 1;
        sX[c*CX_CSTR + row*CX_RSTR + (side ? 68 : 3)] = 0.f;
    }

    auto stageA = [&](int st, int it) {
        int tap = it % 9, cc = it / 9;
        int kc = tap*256 + cc*64;
        uint32_t sb0 = base + (uint32_t)(st*CVA_PLANE*4);
        #pragma unroll
        for (int j = 0; j < 16; j++) {
            int idx = tid + j*256;
            int row = idx >> 4;
            int seg = idx & 15;
            cp16(sb0 + (uint32_t)((row*CVA_STR + seg*4)*4),
                 d_wf + (size_t)row*KCONV + kc + seg*4);
        }
    };
    auto loadX = [&](int cc) {
        #pragma unroll
        for (int j = 0; j < 16; j++) {
            int idx = tid + j*256;
            int c   = idx >> 6;
            int rem = idx & 63;
            int row = rem >> 4;
            int seg = rem & 15;
            int h = h0 - 1 + row;
            int valid = ((unsigned)h < 64u);
            cp16z(xbase + (uint32_t)((c*CX_CSTR + row*CX_RSTR + 4 + seg*4)*4),
                  d_xr + ((size_t)(b*CCH + cc*64 + c))*NPIX + (valid ? h*64 : 0) + seg*4,
                  valid ? 16 : 0);
        }
    };

    float C[32][4];
    #pragma unroll
    for (int i = 0; i < 32; i++)
        #pragma unroll
        for (int j = 0; j < 4; j++) C[i][j] = 0.f;

    loadX(0);
    stageA(0, 0);
    cp_commit();

    for (int it = 0; it < 36; it++) {
        cp_wait<0>();
        __syncthreads();

        int tap = it % 9;
        bool boundary = (tap == 8);
        if (it < 35 && !boundary) { stageA((it+1) & 1, it+1); cp_commit(); }

        int ky = tap/3 - 1;
        int kx = tap - (tap/3)*3 - 1;
        int rowBase = (wn + ky + 1)*CX_RSTR + kx + 4;
        const float* A = smem + (it & 1)*CVA_PLANE;

        #pragma unroll
        for (int ch = 0; ch < 8; ch++) {
            int ko = ch*8 + cq;
            unsigned a[4][4];
            #pragma unroll
            for (int mt = 0; mt < 4; mt++) {
                int m = wm*64 + mt*16 + r;
                a[mt][0] = ldu(&A[m*CVA_STR + ko]);
                a[mt][1] = ldu(&A[(m+8)*CVA_STR + ko]);
                a[mt][2] = ldu(&A[m*CVA_STR + ko + 4]);
                a[mt][3] = ldu(&A[(m+8)*CVA_STR + ko + 4]);
            }
            unsigned bf[8][2];
            #pragma unroll
            for (int nt = 0; nt < 8; nt++) {
                bf[nt][0] = ldu(&sX[ko*CX_CSTR + rowBase + nt*8 + r]);
                bf[nt][1] = ldu(&sX[(ko+4)*CX_CSTR + rowBase + nt*8 + r]);
            }
            #pragma unroll
            for (int mt = 0; mt < 4; mt++)
                #pragma unroll
                for (int nt = 0; nt < 8; nt++)
                    mma_tf32(C[mt*8+nt], a[mt][0], a[mt][1], a[mt][2], a[mt][3],
                             bf[nt][0], bf[nt][1]);
        }

        if (boundary && it < 35) {
            __syncthreads();            // all warps done reading x-tile
            loadX(it/9 + 1);
            stageA((it+1) & 1, it+1);
            cp_commit();
        }
    }

    // epilogue: store + fused GN1 partial stats
    #pragma unroll
    for (int mt = 0; mt < 4; mt++) {
        int m = wm*64 + mt*16 + r;
        float bv0 = sb[m], bv8 = sb[m + 8];
        float s = 0.f, s2 = 0.f;
        #pragma unroll
        for (int nt = 0; nt < 8; nt++) {
            int n = pix0 + wn*64 + nt*8 + 2*cq;
            float* cf = C[mt*8 + nt];
            float v0 = cf[0]+bv0, v1 = cf[1]+bv0, v2 = cf[2]+bv8, v3 = cf[3]+bv8;
            *(float2*)&d_xs[((size_t)(b*CCH + m))*NPIX + n]     = make_float2(v0, v1);
            *(float2*)&d_xs[((size_t)(b*CCH + m + 8))*NPIX + n] = make_float2(v2, v3);
            s  += v0 + v1 + v2 + v3;
            s2 += v0*v0 + v1*v1 + v2*v2 + v3*v3;
        }
        wred2(s, s2);
        if (lane == 0) {
            int bg = b*8 + wm*2 + (mt >> 1);
            atomicAdd(&d_part1[bg*2],     s);
            atomicAdd(&d_part1[bg*2 + 1], s2);
        }
    }
}

// ---------------- GN1 apply + ReLU ----------------------------------------------
__global__ void gn1_apply_kernel(const float* __restrict__ gw,
                                 const float* __restrict__ gb) {
    __shared__ float st[2];
    int b  = blockIdx.z;
    int kp = blockIdx.y;
    int c  = kp << 1;
    int bg = b*8 + (kp >> 4);
    if (threadIdx.x == 0) {
        float S  = d_part1[bg*2];
        float S2 = d_part1[bg*2 + 1];
        float mean = S / (float)GSIZE;
        st[0] = mean;
        st[1] = rsqrtf(S2 / (float)GSIZE - mean*mean + EPSV);
    }
    __syncthreads();
    float sc0 = st[1] * gw[c],   sh0 = gb[c]   - st[0]*sc0;
    float sc1 = st[1] * gw[c+1], sh1 = gb[c+1] - st[0]*sc1;
    int n = blockIdx.x*1024 + threadIdx.x*4;
    size_t base = ((size_t)(b*CCH + c))*NPIX + n;
    float4 v0 = *(float4*)&d_xs[base];
    float4 v1 = *(float4*)&d_xs[base + NPIX];
    v0.x = fmaxf(v0.x*sc0 + sh0, 0.f); v0.y = fmaxf(v0.y*sc0 + sh0, 0.f);
    v0.z = fmaxf(v0.z*sc0 + sh0, 0.f); v0.w = fmaxf(v0.w*sc0 + sh0, 0.f);
    v1.x = fmaxf(v1.x*sc1 + sh1, 0.f); v1.y = fmaxf(v1.y*sc1 + sh1, 0.f);
    v1.z = fmaxf(v1.z*sc1 + sh1, 0.f); v1.w = fmaxf(v1.w*sc1 + sh1, 0.f);
    *(float4*)&d_xs[base]        = v0;
    *(float4*)&d_xs[base + NPIX] = v1;
    uint4 pk;
    pk.x = pack_bf(v1.x, v0.x);
    pk.y = pack_bf(v1.y, v0.y);
    pk.z = pack_bf(v1.z, v0.z);
    pk.w = pack_bf(v1.w, v0.w);
    *(uint4*)&d_xsb[((size_t)(b*128 + kp))*NPIX + n] = pk;
}

// ---------------- bf16 1x1 GEMM ---------------------------------------------------
template<int MODE>
__global__ void __launch_bounds__(256) gemm_bf_kernel(const float* __restrict__ bias0,
                                                      const float* __restrict__ bias1,
                                                      const float* __restrict__ bias2) {
    constexpr int K  = (MODE == 3) ? 128 : 256;
    constexpr int KP = K / 2;
    constexpr int NI = K / 32;
    const unsigned* Wp = d_wpk + (MODE == 3 ? 49152 : 0);
    const unsigned* Xall = (MODE == 3) ? d_yb : d_xsb;

    __shared__ unsigned Ws[2][64*20];
    __shared__ unsigned Xs[2][16*132];

    int b  = blockIdx.z;
    int n0 = blockIdx.x * 128;
    int m0 = blockIdx.y * 64;
    const unsigned* Xb = Xall + (size_t)b * KP * NPIX;

    int tid  = threadIdx.x;
    int lane = tid & 31;
    int wid  = tid >> 5;
    int wm = wid >> 2, wn = wid & 3;
    int r  = lane >> 2, cq = lane & 3;

    int wRow = tid >> 2, wSeg = tid & 3;
    int xRow = tid >> 5, xSeg = tid & 31;
    uint32_t wBase = smem_u32(Ws);
    uint32_t xBase = smem_u32(Xs);

    auto stage = [&](int s, int it) {
        int kp0 = it * 16;
        cp16(wBase + (uint32_t)((s*64*20 + wRow*20 + wSeg*4)*4),
             Wp + (size_t)(m0 + wRow)*KP + kp0 + wSeg*4);
        #pragma unroll
        for (int j = 0; j < 2; j++) {
            int k = xRow + j*8;
            cp16(xBase + (uint32_t)((s*16*132 + k*132 + xSeg*4)*4),
                 Xb + (size_t)(kp0 + k)*NPIX + n0 + xSeg*4);
        }
    };

    float C[8][4];
    #pragma unroll
    for (int i = 0; i < 8; i++)
        #pragma unroll
        for (int j = 0; j < 4; j++) C[i][j] = 0.f;

    stage(0, 0);
    cp_commit();

    for (int it = 0; it < NI; it++) {
        if (it < NI-1) { stage((it+1)&1, it+1); cp_commit(); cp_wait<1>(); }
        else cp_wait<0>();
        __syncthreads();

        const unsigned* Wt = Ws[it & 1];
        const unsigned* Xt = Xs[it & 1];

        #pragma unroll
        for (int ch = 0; ch < 2; ch++) {
            int ko = ch*8 + cq;
            unsigned a[2][4];
            #pragma unroll
            for (int mt = 0; mt < 2; mt++) {
                int mr = wm*32 + mt*16 + r;
                a[mt][0] = Wt[mr*20 + ko];
                a[mt][1] = Wt[(mr+8)*20 + ko];
                a[mt][2] = Wt[mr*20 + ko + 4];
                a[mt][3] = Wt[(mr+8)*20 + ko + 4];
            }
            #pragma unroll
            for (int nt = 0; nt < 4; nt++) {
                int nn = wn*32 + nt*8 + r;
                unsigned b0 = Xt[ko*132 + nn];
                unsigned b1 = Xt[(ko+4)*132 + nn];
                mma_bf16(C[nt],     a[0][0], a[0][1], a[0][2], a[0][3], b0, b1);
                mma_bf16(C[4 + nt], a[1][0], a[1][1], a[1][2], a[1][3], b0, b1);
            }
        }
        __syncthreads();
    }

    const float* bias = (MODE == 3) ? bias0
                      : (m0 < 128 ? bias0 : m0 < 256 ? bias1 : bias2);
    int mbase = (MODE == 3) ? m0 : (m0 & 127);
    __nv_bfloat16* Obf = nullptr;
    if (MODE != 3)
        Obf = (m0 < 128 ? d_thb : m0 < 256 ? d_phb : d_gb) + (size_t)b * CI * NPIX;

    float s = 0.f, s2 = 0.f;
    #pragma unroll
    for (int mt = 0; mt < 2; mt++) {
        int ml = mbase + wm*32 + mt*16 + r;
        float bv0 = bias[ml], bv8 = bias[ml + 8];
        #pragma unroll
        for (int nt = 0; nt < 4; nt++) {
            int n = n0 + wn*32 + nt*8 + 2*cq;
            float* cf = C[mt*4 + nt];
            if (MODE == 3) {
                float v0 = cf[0]+bv0, v1 = cf[1]+bv0, v2 = cf[2]+bv8, v3 = cf[3]+bv8;
                float* Ob = d_z + (size_t)b * CCH * NPIX;
                *(float2*)&Ob[(size_t)ml*NPIX + n]     = make_float2(v0, v1);
                *(float2*)&Ob[(size_t)(ml+8)*NPIX + n] = make_float2(v2, v3);
                s  += v0 + v1 + v2 + v3;
                s2 += v0*v0 + v1*v1 + v2*v2 + v3*v3;
            } else {
                *(unsigned*)&Obf[(size_t)ml*NPIX + n]     = pack_bf(cf[1]+bv0, cf[0]+bv0);
                *(unsigned*)&Obf[(size_t)(ml+8)*NPIX + n] = pack_bf(cf[3]+bv8, cf[2]+bv8);
            }
        }
    }
    if (MODE == 3) {
        wred2(s, s2);
        if (lane == 0) {
            int bg = b*8 + (m0 >> 5) + wm;
            atomicAdd(&d_part2[bg*2],     s);
            atomicAdd(&d_part2[bg*2 + 1], s2);
        }
    }
}

// ---------------- bf16 flash attention --------------------------------------------
#define KS_STR 68
#define KS_STAGE (64*KS_STR)
#define GS_STR 36
#define GS_STAGE (128*GS_STR)
#define ATTN_SMEM ((2*KS_STAGE + 2*GS_STAGE)*4)

__global__ void __launch_bounds__(128, 2) attention_tc_kernel() {
    extern __shared__ float smem[];
    float* sK = smem;
    float* sG = smem + 2*KS_STAGE;

    int b  = blockIdx.y;
    int n0 = blockIdx.x * 64;
    const __nv_bfloat16* Tt = d_ttb + (size_t)b * NPIX * CI;
    const __nv_bfloat16* Pt = d_ptb + (size_t)b * NPIX * CI;
    const __nv_bfloat16* Gp = d_gb  + (size_t)b * CI * NPIX;
    unsigned* Ybu = d_yb + (size_t)b * 64 * NPIX;

    int tid  = threadIdx.x;
    int lane = tid & 31;
    int wid  = tid >> 5;
    int qb   = wid * 16;
    int r    = lane >> 2;
    int cq   = lane & 3;

    uint32_t kBase = smem_u32(sK);
    uint32_t gBase = smem_u32(sG);

    auto stageK = [&](int s, int m0k) {
        #pragma unroll
        for (int j = 0; j < 8; j++) {
            int idx = tid + j*128;
            int row = idx >> 4, seg = idx & 15;
            cp16(kBase + (uint32_t)((s*KS_STAGE + row*KS_STR + seg*4)*4),
                 Pt + (size_t)(m0k + row)*CI + seg*8);
        }
    };
    auto stageG = [&](int s, int m0k) {
        #pragma unroll
        for (int j = 0; j < 8; j++) {
            int idx = tid + j*128;
            int row = idx >> 3, seg = idx & 7;
            cp16(gBase + (uint32_t)((s*GS_STAGE + row*GS_STR + seg*4)*4),
                 Gp + (size_t)row*NPIX + m0k + seg*8);
        }
    };

    #pragma unroll
    for (int j = 0; j < 8; j++) {
        int idx = tid + j*128;
        int row = idx >> 4, seg = idx & 15;
        cp16(kBase + (uint32_t)((row*KS_STR + seg*4)*4),
             Tt + (size_t)(n0 + row)*CI + seg*8);
    }
    cp_commit();
    cp_wait<0>();
    __syncthreads();

    unsigned qa[8][4];
    #pragma unroll
    for (int ch = 0; ch < 8; ch++) {
        int ko = ch*8 + cq;
        qa[ch][0] = ldu(&sK[(qb + r)*KS_STR + ko]);
        qa[ch][1] = ldu(&sK[(qb + r + 8)*KS_STR + ko]);
        qa[ch][2] = ldu(&sK[(qb + r)*KS_STR + ko + 4]);
        qa[ch][3] = ldu(&sK[(qb + r + 8)*KS_STR + ko + 4]);
    }
    __syncthreads();

    stageK(0, 0); cp_commit();
    stageG(0, 0); cp_commit();

    float O[16][4];
    #pragma unroll
    for (int i = 0; i < 16; i++)
        #pragma unroll
        for (int j = 0; j < 4; j++) O[i][j] = 0.f;
    float Mx0 = -1e30f, Mx1 = -1e30f, L0 = 0.f, L1 = 0.f;
    const unsigned FULL = 0xffffffffu;

    for (int t = 0; t < 64; t++) {
        int s = t & 1;
        int m0 = t * 64;

        if (t < 63) { stageK(s^1, m0 + 64); cp_commit(); cp_wait<2>(); }
        else        cp_wait<1>();
        __syncthreads();

        const float* Kt = sK + s*KS_STAGE;
        float S[8][4];
        #pragma unroll
        for (int i = 0; i < 8; i++)
            #pragma unroll
            for (int j = 0; j < 4; j++) S[i][j] = 0.f;

        #pragma unroll
        for (int ch = 0; ch < 8; ch++) {
            int ko = ch*8 + cq;
            #pragma unroll
            for (int nt = 0; nt < 8; nt++) {
                unsigned b0 = ldu(&Kt[(nt*8 + r)*KS_STR + ko]);
                unsigned b1 = ldu(&Kt[(nt*8 + r)*KS_STR + ko + 4]);
                mma_bf16(S[nt], qa[ch][0], qa[ch][1], qa[ch][2], qa[ch][3], b0, b1);
            }
        }

        float rm0 = -1e30f, rm1 = -1e30f;
        #pragma unroll
        for (int nt = 0; nt < 8; nt++) {
            rm0 = fmaxf(rm0, fmaxf(S[nt][0], S[nt][1]));
            rm1 = fmaxf(rm1, fmaxf(S[nt][2], S[nt][3]));
        }
        rm0 = fmaxf(rm0, __shfl_xor_sync(FULL, rm0, 1));
        rm0 = fmaxf(rm0, __shfl_xor_sync(FULL, rm0, 2));
        rm1 = fmaxf(rm1, __shfl_xor_sync(FULL, rm1, 1));
        rm1 = fmaxf(rm1, __shfl_xor_sync(FULL, rm1, 2));

        float nm0 = fmaxf(Mx0, rm0), nm1 = fmaxf(Mx1, rm1);
        float sc0 = __expf(Mx0 - nm0), sc1 = __expf(Mx1 - nm1);
        Mx0 = nm0; Mx1 = nm1;

        float rs0 = 0.f, rs1 = 0.f;
        #pragma unroll
        for (int nt = 0; nt < 8; nt++) {
            S[nt][0] = __expf(S[nt][0] - nm0);
            S[nt][1] = __expf(S[nt][1] - nm0);
            S[nt][2] = __expf(S[nt][2] - nm1);
            S[nt][3] = __expf(S[nt][3] - nm1);
            rs0 += S[nt][0] + S[nt][1];
            rs1 += S[nt][2] + S[nt][3];
        }
        rs0 += __shfl_xor_sync(FULL, rs0, 1);
        rs0 += __shfl_xor_sync(FULL, rs0, 2);
        rs1 += __shfl_xor_sync(FULL, rs1, 1);
        rs1 += __shfl_xor_sync(FULL, rs1, 2);
        L0 = L0*sc0 + rs0;
        L1 = L1*sc1 + rs1;

        if (!__all_sync(FULL, (sc0 == 1.f) & (sc1 == 1.f))) {
            #pragma unroll
            for (int i = 0; i < 16; i++) {
                O[i][0] *= sc0; O[i][1] *= sc0;
                O[i][2] *= sc1; O[i][3] *= sc1;
            }
        }

        unsigned pa[4][4];
        #pragma unroll
        for (int kc = 0; kc < 4; kc++) {
            pa[kc][0] = pack_bf(S[2*kc][1],   S[2*kc][0]);
            pa[kc][1] = pack_bf(S[2*kc][3],   S[2*kc][2]);
            pa[kc][2] = pack_bf(S[2*kc+1][1], S[2*kc+1][0]);
            pa[kc][3] = pack_bf(S[2*kc+1][3], S[2*kc+1][2]);
        }

        if (t < 63) { stageG(s^1, m0 + 64); cp_commit(); cp_wait<2>(); }
        else        cp_wait<0>();
        __syncthreads();

        const float* Gt = sG + s*GS_STAGE;
        #pragma unroll
        for (int kc = 0; kc < 4; kc++) {
            int ko = kc*8 + cq;
            #pragma unroll
            for (int ct = 0; ct < 16; ct++) {
                unsigned b0 = ldu(&Gt[(ct*8 + r)*GS_STR + ko]);
                unsigned b1 = ldu(&Gt[(ct*8 + r)*GS_STR + ko + 4]);
                mma_bf16(O[ct], pa[kc][0], pa[kc][1], pa[kc][2], pa[kc][3], b0, b1);
            }
        }
    }

    float inv0 = 1.0f / L0, inv1 = 1.0f / L1;
    int q = n0 + qb + r;
    #pragma unroll
    for (int ct = 0; ct < 16; ct++) {
        int kp = ct*4 + cq;
        Ybu[(size_t)kp*NPIX + q]     = pack_bf(O[ct][1]*inv0, O[ct][0]*inv0);
        Ybu[(size_t)kp*NPIX + q + 8] = pack_bf(O[ct][3]*inv1, O[ct][2]*inv1);
    }
}

// ---------------- final: out = GN2(z)*0.1 + xs ------------------------------------
__global__ void final_apply_kernel(const float* __restrict__ gw,
                                   const float* __restrict__ gb,
                                   float* __restrict__ out) {
    __shared__ float st[2];
    int bg = blockIdx.x >> 7;
    if (threadIdx.x == 0) {
        float S  = d_part2[bg*2];
        float S2 = d_part2[bg*2 + 1];
        float mean = S / (float)GSIZE;
        st[0] = mean;
        st[1] = rsqrtf(S2 / (float)GSIZE - mean*mean + EPSV);
    }
    __syncthreads();
    int i4 = blockIdx.x * blockDim.x + threadIdx.x;
    int idx = i4 << 2;
    int c   = (idx >> 12) & 255;
    float sc = st[1] * gw[c];
    float sh = gb[c] - st[0] * sc;
    float4 z = ((const float4*)d_z)[i4];
    float4 xs = ((const float4*)d_xs)[i4];
    float4 o;
    o.x = (z.x*sc + sh)*0.1f + xs.x;
    o.y = (z.y*sc + sh)*0.1f + xs.y;
    o.z = (z.z*sc + sh)*0.1f + xs.z;
    o.w = (z.w*sc + sh)*0.1f + xs.w;
    ((float4*)out)[i4] = o;
}

// ---------------- launch -----------------------------------------------------------
extern "C" void kernel_launch(void* const* d_in, const int* in_sizes, int n_in,
                              void* d_out, int out_size) {
    const float* x    = (const float*)d_in[0];
    const float* sw   = (const float*)d_in[1];
    const float* sb   = (const float*)d_in[2];
    const float* gn1w = (const float*)d_in[3];
    const float* gn1b = (const float*)d_in[4];
    const float* g_w  = (const float*)d_in[5];
    const float* g_b  = (const float*)d_in[6];
    const float* th_w = (const float*)d_in[7];
    const float* th_b = (const float*)d_in[8];
    const float* ph_w = (const float*)d_in[9];
    const float* ph_b = (const float*)d_in[10];
    const float* w_w  = (const float*)d_in[11];
    const float* w_b  = (const float*)d_in[12];
    const float* gn2w = (const float*)d_in[13];
    const float* gn2b = (const float*)d_in[14];
    float* out = (float*)d_out;

    static int attrSet = 0;
    if (!attrSet) {
        cudaFuncSetAttribute(conv_tc_kernel,
                             cudaFuncAttributeMaxDynamicSharedMemorySize, CONV_SMEM);
        cudaFuncSetAttribute(attention_tc_kernel,
                             cudaFuncAttributeMaxDynamicSharedMemorySize, ATTN_SMEM);
        attrSet = 1;
    }

    pack_wf_kernel<<<dim3(9, 256), 256>>>(sw);
    pack_qkvw_kernel<<<256, 256>>>(th_w, ph_w, g_w, w_w);
    round_x_kernel<<<4096, 256>>>(x);
    conv_tc_kernel<<<dim3(32, 4), 256, CONV_SMEM>>>(sb);
    gn1_apply_kernel<<<dim3(4, 128, 4), 256>>>(gn1w, gn1b);

    gemm_bf_kernel<0><<<dim3(32, 6, 4), 256>>>(th_b, ph_b, g_b);
    prep_attn_kernel<<<dim3(128, 4, 8), dim3(32, 8)>>>();

    attention_tc_kernel<<<dim3(64, 4), 128, ATTN_SMEM>>>();

    gemm_bf_kernel<3><<<dim3(32, 4, 4), 256>>>(w_b, nullptr, nullptr);
    final_apply_kernel<<<4096, 256>>>(gn2w, gn2b, out);

    (void)in_sizes; (void)n_in; (void)out_size;
}